// round 5
// baseline (speedup 1.0000x reference)
#include <cuda_runtime.h>
#include <cuda_bf16.h>
#include <cstdint>

// ---------------- problem constants ----------------
#define NROWS 8192           // 2 * 4096
#define HALF  4096
#define DIM   256
#define PK    512            // physical row: [hi(256) | lo(256)] bf16
#define PROWB 1024           // physical row bytes
#define KTILES 12            // logical K = 768 in chunks of 64 bf16 (128B)
#define BM 128
#define BN 256
#define NSTAGE 4
#define NBLK 64              // 128-row blocks
#define NCOL  32             // 256-col blocks
#define NTILES 1056          // sum_{bi<64} (32 - bi/2)

#define STAGE_BYTES 49152    // A 16KB + B 32KB
#define DSM_BYTES (NSTAGE * STAGE_BYTES)

// ---------------- device scratch ----------------
__device__ double g_S1;
__device__ float  g_colsum[DIM];
__device__ float  g_sq[NROWS];
__device__ float  g_negc;            // -log2(e)/(16*bandwidth)
__device__ double g_acc;
__device__ __align__(16) __nv_bfloat16 g_X[(size_t)NROWS * PK];  // [hi|lo]

__constant__ int c_secA[3] = {0, 0, 1};   // A logical sections: hi,hi,lo
__constant__ int c_secB[3] = {0, 1, 0};   // B logical sections: hi,lo,hi

// ---------------- PTX helpers (base ISA only) ----------------
__device__ __forceinline__ float ex2f(float x) {
    float y; asm("ex2.approx.f32 %0, %1;" : "=f"(y) : "f"(x)); return y;
}
__device__ __forceinline__ uint32_t smem_u32(const void* p) {
    uint32_t a;
    asm("{ .reg .u64 t; cvta.to.shared.u64 t, %1; cvt.u32.u64 %0, t; }" : "=r"(a) : "l"(p));
    return a;
}
__device__ __forceinline__ void cp16(uint32_t saddr, const void* g) {
    asm volatile("cp.async.cg.shared.global [%0], [%1], 16;" :: "r"(saddr), "l"(g));
}
#define CP_COMMIT() asm volatile("cp.async.commit_group;" ::: "memory")
#define CP_WAIT2()  asm volatile("cp.async.wait_group 2;" ::: "memory")

__device__ __forceinline__ void ldsm4(uint32_t* r, uint32_t addr) {
    asm volatile("ldmatrix.sync.aligned.m8n8.x4.shared.b16 {%0,%1,%2,%3}, [%4];"
        : "=r"(r[0]), "=r"(r[1]), "=r"(r[2]), "=r"(r[3]) : "r"(addr));
}
__device__ __forceinline__ void mma16816(float* c, const uint32_t* a,
                                         uint32_t b0, uint32_t b1) {
    asm volatile(
        "mma.sync.aligned.m16n8k16.row.col.f32.bf16.bf16.f32 "
        "{%0,%1,%2,%3}, {%4,%5,%6,%7}, {%8,%9}, {%0,%1,%2,%3};"
        : "+f"(c[0]), "+f"(c[1]), "+f"(c[2]), "+f"(c[3])
        : "r"(a[0]), "r"(a[1]), "r"(a[2]), "r"(a[3]), "r"(b0), "r"(b1));
}
__device__ __forceinline__ uint32_t pack_bf16(float x, float y) {
    __nv_bfloat162 t = __floats2bfloat162_rn(x, y);
    return *reinterpret_cast<uint32_t*>(&t);
}

// ---------------------------------------------------------------------------
// k0: zero accumulators (launch #1)
// ---------------------------------------------------------------------------
__global__ void k0_zero() {
    int tid = threadIdx.x;
    if (tid == 0) g_S1 = 0.0;
    if (tid < DIM) g_colsum[tid] = 0.0f;
}

// ---------------------------------------------------------------------------
// k1f: fused rowstats + hi/lo bf16 split (launch #2). One warp per row.
// ---------------------------------------------------------------------------
__global__ void k1f(const float* __restrict__ src,
                    const float* __restrict__ tgt) {
    __shared__ float cs[DIM];
    __shared__ float s1p[8];
    int tid = threadIdx.x, warp = tid >> 5, lane = tid & 31;
    cs[tid] = 0.0f;
    __syncthreads();

    int row = blockIdx.x * 8 + warp;
    const float* p = (row < HALF) ? (src + (size_t)row * DIM)
                                  : (tgt + (size_t)(row - HALF) * DIM);
    const float4* p4 = (const float4*)p;
    float4 v0 = p4[lane];        // cols 4*lane..+3
    float4 v1 = p4[lane + 32];   // cols 128+4*lane..+3

    float vv[8] = { v0.x, v0.y, v0.z, v0.w, v1.x, v1.y, v1.z, v1.w };
    float h[8], l[8];
    float ss = 0.0f;
    #pragma unroll
    for (int i = 0; i < 8; i++) {
        h[i] = __bfloat162float(__float2bfloat16(vv[i]));
        l[i] = vv[i] - h[i];
        ss = fmaf(vv[i], vv[i], ss);
    }
    #pragma unroll
    for (int o = 16; o; o >>= 1) ss += __shfl_xor_sync(0xffffffffu, ss, o);
    if (lane == 0) { g_sq[row] = ss; s1p[warp] = ss; }

    // packed bf16 stores: [hi(256)|lo(256)] per row, v0->first 256B of section
    char* base = (char*)g_X + (size_t)row * PROWB + 8 * lane;
    uint2 hv0 = { pack_bf16(vv[0], vv[1]), pack_bf16(vv[2], vv[3]) };
    uint2 hv1 = { pack_bf16(vv[4], vv[5]), pack_bf16(vv[6], vv[7]) };
    uint2 lv0 = { pack_bf16(l[0], l[1]),  pack_bf16(l[2], l[3]) };
    uint2 lv1 = { pack_bf16(l[4], l[5]),  pack_bf16(l[6], l[7]) };
    *(uint2*)(base)       = hv0;
    *(uint2*)(base + 256) = hv1;
    *(uint2*)(base + 512) = lv0;
    *(uint2*)(base + 768) = lv1;

    int c0 = 4 * lane;
    atomicAdd(&cs[c0 + 0], v0.x); atomicAdd(&cs[c0 + 1], v0.y);
    atomicAdd(&cs[c0 + 2], v0.z); atomicAdd(&cs[c0 + 3], v0.w);
    atomicAdd(&cs[128 + c0 + 0], v1.x); atomicAdd(&cs[128 + c0 + 1], v1.y);
    atomicAdd(&cs[128 + c0 + 2], v1.z); atomicAdd(&cs[128 + c0 + 3], v1.w);
    __syncthreads();

    if (tid == 0) {
        double s = 0.0;
        #pragma unroll
        for (int w = 0; w < 8; w++) s += (double)s1p[w];
        atomicAdd(&g_S1, s);
    }
    atomicAdd(&g_colsum[tid], cs[tid]);
}

// ---------------------------------------------------------------------------
// k2: bandwidth closed form (launch #3)
// ---------------------------------------------------------------------------
__global__ void k2_bandwidth() {
    __shared__ float red[DIM];
    int tid = threadIdx.x;
    float c = g_colsum[tid];
    red[tid] = c * c;
    __syncthreads();
    for (int s = 128; s; s >>= 1) { if (tid < s) red[tid] += red[tid + s]; __syncthreads(); }
    if (tid == 0) {
        const double N = (double)NROWS;
        double sum_l2 = 2.0 * N * g_S1 - 2.0 * (double)red[0];
        double bw = sum_l2 / (N * N - N);
        bw = bw / 4.0;                      // KERNEL_MUL^(KERNEL_NUM//2)
        g_negc = (float)(-1.4426950408889634 / (16.0 * bw));
        g_acc = 0.0;
    }
}

// ---------------------------------------------------------------------------
// k3: block-triangular 128x256 Gram GEMM (mma.sync bf16) + fused RBF epilogue
//     (launch #4 -> profiled). 256 thr, warp tile 64x64, 4-stage cp.async.
// ---------------------------------------------------------------------------
__global__ void __launch_bounds__(256, 1) k3_mma() {
    extern __shared__ char dsm[];
    uint32_t smbase = smem_u32(dsm);

    __shared__ float sqic[BM];
    __shared__ float sqjc[BN];
    __shared__ float redw[8];

    int tid = threadIdx.x, wid = tid >> 5, lane = tid & 31;

    // map linear id -> (bi 128-row block, c 256-col block), 2c+1 >= bi
    int t = blockIdx.x;
    int bi = 0, cnt = 32;
    #pragma unroll 1
    while (t >= cnt) { t -= cnt; bi++; cnt = 32 - (bi >> 1); }
    int c = (bi >> 1) + t;
    int i0 = bi * BM, j0 = c * BN;

    const char* Ag = (const char*)g_X + (size_t)i0 * PROWB;
    const char* Bg = (const char*)g_X + (size_t)j0 * PROWB;

    int lrow = tid >> 3;          // 0..31
    int lq   = tid & 7;           // 16B chunk in a 128B row
    uint32_t lo0 = (uint32_t)(lrow * 128 + lq * 16);

    // stage loader: A 128 rows, B 256 rows of the chunk's 128 bytes
    auto issue_stage = [&](int ck, int buf) {
        uint32_t smA = smbase + buf * STAGE_BYTES;
        uint32_t smB = smA + 16384;
        int grp = ck >> 2, sub = ck & 3;
        const char* ga = Ag + c_secA[grp] * 512 + sub * 128 + lq * 16;
        const char* gb = Bg + c_secB[grp] * 512 + sub * 128 + lq * 16;
        #pragma unroll
        for (int i = 0; i < 4; i++) {
            uint32_t o = lo0 + (uint32_t)(i * 32 * 128);
            uint32_t sw = o ^ ((o >> 3) & 0x70);
            cp16(smA + sw, ga + (size_t)(lrow + 32 * i) * PROWB);
        }
        #pragma unroll
        for (int i = 0; i < 8; i++) {
            uint32_t o = lo0 + (uint32_t)(i * 32 * 128);
            uint32_t sw = o ^ ((o >> 3) & 0x70);
            cp16(smB + sw, gb + (size_t)(lrow + 32 * i) * PROWB);
        }
    };

    #pragma unroll
    for (int s = 0; s < NSTAGE - 1; s++) { issue_stage(s, s); CP_COMMIT(); }

    float negc = g_negc;
    if (tid < 128) sqic[tid] = g_sq[i0 + tid] * negc;
    sqjc[tid] = g_sq[j0 + tid] * negc;

    // warp tiling: 2(m) x 4(n), warp tile 64x64
    int wm = wid >> 2, wn = wid & 3;

    uint32_t arow[4], av[4];
    #pragma unroll
    for (int tm = 0; tm < 4; tm++) {
        uint32_t o = (uint32_t)((wm * 64 + tm * 16 + (lane & 15)) * 128);
        arow[tm] = o; av[tm] = (o >> 3) & 0x70;
    }
    uint32_t brow[4], bv[4];
    #pragma unroll
    for (int tg = 0; tg < 4; tg++) {
        uint32_t o = (uint32_t)((wn * 64 + tg * 16 + (lane & 15)) * 128);
        brow[tg] = o; bv[tg] = (o >> 3) & 0x70;
    }
    uint32_t ksel = (uint32_t)(lane & 16);

    float acc[4][8][4];
    #pragma unroll
    for (int a = 0; a < 4; a++)
        #pragma unroll
        for (int b = 0; b < 8; b++)
            #pragma unroll
            for (int e = 0; e < 4; e++) acc[a][b][e] = 0.0f;

    for (int it = 0; it < KTILES; it++) {
        CP_WAIT2();
        __syncthreads();

        int ld = it + NSTAGE - 1;
        if (ld < KTILES) issue_stage(ld, ld & 3);
        CP_COMMIT();

        uint32_t smA = smbase + (it & 3) * STAGE_BYTES;
        uint32_t smB = smA + 16384;

        #pragma unroll
        for (int ks = 0; ks < 4; ks++) {
            uint32_t kb = (uint32_t)(ks * 32) + ksel;
            uint32_t a[4][4], b[4][4];
            #pragma unroll
            for (int tm = 0; tm < 4; tm++)
                ldsm4(a[tm], smA + arow[tm] + (kb ^ av[tm]));
            #pragma unroll
            for (int tg = 0; tg < 4; tg++)
                ldsm4(b[tg], smB + brow[tg] + (kb ^ bv[tg]));
            #pragma unroll
            for (int tm = 0; tm < 4; tm++)
                #pragma unroll
                for (int tg = 0; tg < 4; tg++) {
                    mma16816(acc[tm][2*tg],   a[tm], b[tg][0], b[tg][2]);
                    mma16816(acc[tm][2*tg+1], a[tm], b[tg][1], b[tg][3]);
                }
        }
        __syncthreads();
    }

    // fused RBF epilogue; per-warp weight by column 128-half
    int h = 2 * c + (wn >> 1);           // this warp's 128-col block index
    float w = (h < bi) ? 0.0f : ((h == bi) ? 1.0f : 2.0f);
    float sign = ((bi < 32) == (h < 32)) ? 1.0f : -1.0f;

    float tsum = 0.0f;
    if (w != 0.0f) {
        float twoc = -2.0f * negc;
        #pragma unroll
        for (int tm = 0; tm < 4; tm++) {
            int mb = wm * 64 + tm * 16 + (lane >> 2);
            float si0 = sqic[mb], si8 = sqic[mb + 8];
            #pragma unroll
            for (int tn = 0; tn < 8; tn++) {
                int nb = wn * 64 + tn * 8 + (lane & 3) * 2;
                float sj0 = sqjc[nb], sj1 = sqjc[nb + 1];
                float* cc = acc[tm][tn];
                float base[4] = { si0 + sj0, si0 + sj1, si8 + sj0, si8 + sj1 };
                #pragma unroll
                for (int e = 0; e < 4; e++) {
                    float arg = fmaf(cc[e], twoc, base[e]);
                    float u = ex2f(arg);
                    float u2 = u * u, u4 = u2 * u2, u8 = u4 * u4, u16 = u8 * u8;
                    tsum += ((u + u2) + (u4 + u8)) + u16;
                }
            }
        }
    }
    #pragma unroll
    for (int o = 16; o; o >>= 1) tsum += __shfl_xor_sync(0xffffffffu, tsum, o);
    if (lane == 0) redw[wid] = tsum * w * sign;
    __syncthreads();
    if (tid == 0) {
        float s = ((redw[0] + redw[1]) + (redw[2] + redw[3]))
                + ((redw[4] + redw[5]) + (redw[6] + redw[7]));
        atomicAdd(&g_acc, (double)s);
    }
}

// ---------------------------------------------------------------------------
// k4: finalize mean (launch #5)
// ---------------------------------------------------------------------------
__global__ void k4_final(float* out) {
    if (threadIdx.x == 0)
        out[0] = (float)(g_acc / ((double)HALF * (double)HALF));
}

extern "C" void kernel_launch(void* const* d_in, const int* in_sizes, int n_in,
                              void* d_out, int out_size) {
    const float* src = (const float*)d_in[0];
    const float* tgt = (const float*)d_in[1];
    float* out = (float*)d_out;

    cudaFuncSetAttribute(k3_mma, cudaFuncAttributeMaxDynamicSharedMemorySize, DSM_BYTES);

    k0_zero<<<1, 256>>>();
    k1f<<<NROWS / 8, 256>>>(src, tgt);
    k2_bandwidth<<<1, 256>>>();
    k3_mma<<<NTILES, 256, DSM_BYTES>>>();
    k4_final<<<1, 32>>>(out);
}

// round 6
// speedup vs baseline: 1.8821x; 1.8821x over previous
#include <cuda_runtime.h>
#include <cuda_bf16.h>
#include <cstdint>

// ---------------- problem constants ----------------
#define NROWS 8192           // 2 * 4096
#define HALF  4096
#define DIM   256
#define PROWB 1024           // physical row bytes: [hi(512B) | lo(512B)]
#define KTILES 12            // logical K = 768 bf16, chunks of 64 (128B)
#define BM 128
#define BN 128
#define NSTAGE 3
#define NBLK 64
#define NTILES (NBLK * (NBLK + 1) / 2)   // 2080

#define STAGE_BYTES 32768    // A 16KB + B 16KB
#define DSM_BYTES (NSTAGE * STAGE_BYTES) // 96KB -> 2 CTAs/SM

// ---------------- device scratch ----------------
__device__ double g_S1;
__device__ float  g_colsum[DIM];
__device__ float  g_sq[NROWS];
__device__ float  g_negc;            // -log2(e)/(16*bandwidth)
__device__ double g_acc;
__device__ __align__(16) __nv_bfloat16 g_X[(size_t)NROWS * 512]; // [hi|lo]

__constant__ int c_secA[3] = {0, 0, 1};   // A sections: hi,hi,lo
__constant__ int c_secB[3] = {0, 1, 0};   // B sections: hi,lo,hi

// ---------------- PTX helpers (base ISA only) ----------------
__device__ __forceinline__ float ex2f(float x) {
    float y; asm("ex2.approx.f32 %0, %1;" : "=f"(y) : "f"(x)); return y;
}
__device__ __forceinline__ uint32_t smem_u32(const void* p) {
    uint32_t a;
    asm("{ .reg .u64 t; cvta.to.shared.u64 t, %1; cvt.u32.u64 %0, t; }" : "=r"(a) : "l"(p));
    return a;
}
__device__ __forceinline__ void cp16(uint32_t saddr, const void* g) {
    asm volatile("cp.async.cg.shared.global [%0], [%1], 16;" :: "r"(saddr), "l"(g));
}
#define CP_COMMIT() asm volatile("cp.async.commit_group;" ::: "memory")
#define CP_WAIT1()  asm volatile("cp.async.wait_group 1;" ::: "memory")

__device__ __forceinline__ void ldsm4(uint32_t* r, uint32_t addr) {
    asm volatile("ldmatrix.sync.aligned.m8n8.x4.shared.b16 {%0,%1,%2,%3}, [%4];"
        : "=r"(r[0]), "=r"(r[1]), "=r"(r[2]), "=r"(r[3]) : "r"(addr));
}
__device__ __forceinline__ void mma16816(float* c, const uint32_t* a,
                                         uint32_t b0, uint32_t b1) {
    asm volatile(
        "mma.sync.aligned.m16n8k16.row.col.f32.bf16.bf16.f32 "
        "{%0,%1,%2,%3}, {%4,%5,%6,%7}, {%8,%9}, {%0,%1,%2,%3};"
        : "+f"(c[0]), "+f"(c[1]), "+f"(c[2]), "+f"(c[3])
        : "r"(a[0]), "r"(a[1]), "r"(a[2]), "r"(a[3]), "r"(b0), "r"(b1));
}
__device__ __forceinline__ uint32_t pack_bf16(float x, float y) {
    __nv_bfloat162 t = __floats2bfloat162_rn(x, y);
    return *reinterpret_cast<uint32_t*>(&t);
}

// ---------------------------------------------------------------------------
// k0: zero accumulators (launch #1)
// ---------------------------------------------------------------------------
__global__ void k0_zero() {
    int tid = threadIdx.x;
    if (tid == 0) g_S1 = 0.0;
    if (tid < DIM) g_colsum[tid] = 0.0f;
}

// ---------------------------------------------------------------------------
// k1f: fused rowstats + hi/lo bf16 split (launch #2). One warp per row.
// ---------------------------------------------------------------------------
__global__ void k1f(const float* __restrict__ src,
                    const float* __restrict__ tgt) {
    __shared__ float cs[DIM];
    __shared__ float s1p[8];
    int tid = threadIdx.x, warp = tid >> 5, lane = tid & 31;
    cs[tid] = 0.0f;
    __syncthreads();

    int row = blockIdx.x * 8 + warp;
    const float* p = (row < HALF) ? (src + (size_t)row * DIM)
                                  : (tgt + (size_t)(row - HALF) * DIM);
    const float4* p4 = (const float4*)p;
    float4 v0 = p4[lane];
    float4 v1 = p4[lane + 32];

    float vv[8] = { v0.x, v0.y, v0.z, v0.w, v1.x, v1.y, v1.z, v1.w };
    float l[8];
    float ss = 0.0f;
    #pragma unroll
    for (int i = 0; i < 8; i++) {
        float h = __bfloat162float(__float2bfloat16(vv[i]));
        l[i] = vv[i] - h;
        ss = fmaf(vv[i], vv[i], ss);
    }
    #pragma unroll
    for (int o = 16; o; o >>= 1) ss += __shfl_xor_sync(0xffffffffu, ss, o);
    if (lane == 0) { g_sq[row] = ss; s1p[warp] = ss; }

    char* base = (char*)g_X + (size_t)row * PROWB + 8 * lane;
    uint2 hv0 = { pack_bf16(vv[0], vv[1]), pack_bf16(vv[2], vv[3]) };
    uint2 hv1 = { pack_bf16(vv[4], vv[5]), pack_bf16(vv[6], vv[7]) };
    uint2 lv0 = { pack_bf16(l[0], l[1]),  pack_bf16(l[2], l[3]) };
    uint2 lv1 = { pack_bf16(l[4], l[5]),  pack_bf16(l[6], l[7]) };
    *(uint2*)(base)       = hv0;
    *(uint2*)(base + 256) = hv1;
    *(uint2*)(base + 512) = lv0;
    *(uint2*)(base + 768) = lv1;

    int c0 = 4 * lane;
    atomicAdd(&cs[c0 + 0], v0.x); atomicAdd(&cs[c0 + 1], v0.y);
    atomicAdd(&cs[c0 + 2], v0.z); atomicAdd(&cs[c0 + 3], v0.w);
    atomicAdd(&cs[128 + c0 + 0], v1.x); atomicAdd(&cs[128 + c0 + 1], v1.y);
    atomicAdd(&cs[128 + c0 + 2], v1.z); atomicAdd(&cs[128 + c0 + 3], v1.w);
    __syncthreads();

    if (tid == 0) {
        double s = 0.0;
        #pragma unroll
        for (int w = 0; w < 8; w++) s += (double)s1p[w];
        atomicAdd(&g_S1, s);
    }
    atomicAdd(&g_colsum[tid], cs[tid]);
}

// ---------------------------------------------------------------------------
// k2: bandwidth closed form (launch #3)
// ---------------------------------------------------------------------------
__global__ void k2_bandwidth() {
    __shared__ float red[DIM];
    int tid = threadIdx.x;
    float c = g_colsum[tid];
    red[tid] = c * c;
    __syncthreads();
    for (int s = 128; s; s >>= 1) { if (tid < s) red[tid] += red[tid + s]; __syncthreads(); }
    if (tid == 0) {
        const double N = (double)NROWS;
        double sum_l2 = 2.0 * N * g_S1 - 2.0 * (double)red[0];
        double bw = sum_l2 / (N * N - N);
        bw = bw / 4.0;
        g_negc = (float)(-1.4426950408889634 / (16.0 * bw));
        g_acc = 0.0;
    }
}

// ---------------------------------------------------------------------------
// k3: block-triangular 128x128 Gram GEMM (mma.sync bf16) + fused RBF epilogue
//     (launch #4 -> profiled). 256 thr, 2x4 warps of 64x32, 3-stage cp.async,
//     2 CTAs/SM.
// ---------------------------------------------------------------------------
__global__ void __launch_bounds__(256, 2) k3_mma() {
    extern __shared__ char dsm[];
    uint32_t smbase = smem_u32(dsm);

    __shared__ float sqic[BM];
    __shared__ float sqjc[BN];
    __shared__ float redw[8];

    int tid = threadIdx.x, wid = tid >> 5, lane = tid & 31;

    // linear block id -> upper-triangle (bi, bj), bj >= bi
    int t = blockIdx.x;
    int bi = 0;
    #pragma unroll 1
    while (t >= NBLK - bi) { t -= NBLK - bi; bi++; }
    int bj = bi + t;
    int i0 = bi * BM, j0 = bj * BN;

    const char* Ag = (const char*)g_X + (size_t)i0 * PROWB;
    const char* Bg = (const char*)g_X + (size_t)j0 * PROWB;

    int lrow = tid >> 3;          // 0..31
    int lq   = tid & 7;
    uint32_t lo0 = (uint32_t)(lrow * 128 + lq * 16);

    auto issue_stage = [&](int ck, int buf) {
        uint32_t smA = smbase + buf * STAGE_BYTES;
        uint32_t smB = smA + 16384;
        int grp = ck >> 2, sub = ck & 3;
        const char* ga = Ag + c_secA[grp] * 512 + sub * 128 + lq * 16;
        const char* gb = Bg + c_secB[grp] * 512 + sub * 128 + lq * 16;
        #pragma unroll
        for (int i = 0; i < 4; i++) {
            uint32_t o = lo0 + (uint32_t)(i * 32 * 128);
            uint32_t sw = o ^ ((o >> 3) & 0x70);
            cp16(smA + sw, ga + (size_t)(lrow + 32 * i) * PROWB);
            cp16(smB + sw, gb + (size_t)(lrow + 32 * i) * PROWB);
        }
    };

    issue_stage(0, 0); CP_COMMIT();
    issue_stage(1, 1); CP_COMMIT();

    float negc = g_negc;
    if (tid < 128) sqic[tid] = g_sq[i0 + tid] * negc;
    else           sqjc[tid - 128] = g_sq[j0 + tid - 128] * negc;

    // warp tiling: 2(m) x 4(n), warp tile 64x32
    int wm = wid >> 2, wn = wid & 3;

    uint32_t arow[4], av[4];
    #pragma unroll
    for (int tm = 0; tm < 4; tm++) {
        uint32_t o = (uint32_t)((wm * 64 + tm * 16 + (lane & 15)) * 128);
        arow[tm] = o; av[tm] = (o >> 3) & 0x70;
    }
    uint32_t brow[2], bv[2];
    #pragma unroll
    for (int tg = 0; tg < 2; tg++) {
        uint32_t o = (uint32_t)((wn * 32 + tg * 16 + (lane & 15)) * 128);
        brow[tg] = o; bv[tg] = (o >> 3) & 0x70;
    }
    uint32_t ksel = (uint32_t)(lane & 16);

    float acc[4][4][4];
    #pragma unroll
    for (int a = 0; a < 4; a++)
        #pragma unroll
        for (int b = 0; b < 4; b++)
            #pragma unroll
            for (int e = 0; e < 4; e++) acc[a][b][e] = 0.0f;

    int buf = 0, ldbuf = 2;
    for (int it = 0; it < KTILES; it++) {
        CP_WAIT1();
        __syncthreads();

        int ld = it + NSTAGE - 1;
        if (ld < KTILES) issue_stage(ld, ldbuf);
        CP_COMMIT();

        uint32_t smA = smbase + buf * STAGE_BYTES;
        uint32_t smB = smA + 16384;

        #pragma unroll
        for (int ks = 0; ks < 4; ks++) {
            uint32_t kb = (uint32_t)(ks * 32) + ksel;
            uint32_t a[4][4], b[2][4];
            #pragma unroll
            for (int tm = 0; tm < 4; tm++)
                ldsm4(a[tm], smA + arow[tm] + (kb ^ av[tm]));
            #pragma unroll
            for (int tg = 0; tg < 2; tg++)
                ldsm4(b[tg], smB + brow[tg] + (kb ^ bv[tg]));
            #pragma unroll
            for (int tm = 0; tm < 4; tm++) {
                mma16816(acc[tm][0], a[tm], b[0][0], b[0][2]);
                mma16816(acc[tm][1], a[tm], b[0][1], b[0][3]);
                mma16816(acc[tm][2], a[tm], b[1][0], b[1][2]);
                mma16816(acc[tm][3], a[tm], b[1][1], b[1][3]);
            }
        }
        __syncthreads();
        buf = (buf == NSTAGE - 1) ? 0 : buf + 1;
        ldbuf = (ldbuf == NSTAGE - 1) ? 0 : ldbuf + 1;
    }

    // fused RBF epilogue
    float twoc = -2.0f * negc;
    float tsum = 0.0f;
    #pragma unroll
    for (int tm = 0; tm < 4; tm++) {
        int mb = wm * 64 + tm * 16 + (lane >> 2);
        float si0 = sqic[mb], si8 = sqic[mb + 8];
        #pragma unroll
        for (int tn = 0; tn < 4; tn++) {
            int nb = wn * 32 + tn * 8 + (lane & 3) * 2;
            float sj0 = sqjc[nb], sj1 = sqjc[nb + 1];
            float* cc = acc[tm][tn];
            float base[4] = { si0 + sj0, si0 + sj1, si8 + sj0, si8 + sj1 };
            #pragma unroll
            for (int e = 0; e < 4; e++) {
                float arg = fmaf(cc[e], twoc, base[e]);
                float u = ex2f(arg);
                float u2 = u * u, u4 = u2 * u2, u8 = u4 * u4, u16 = u8 * u8;
                tsum += ((u + u2) + (u4 + u8)) + u16;
            }
        }
    }
    #pragma unroll
    for (int o = 16; o; o >>= 1) tsum += __shfl_xor_sync(0xffffffffu, tsum, o);
    if (lane == 0) redw[wid] = tsum;
    __syncthreads();
    if (tid == 0) {
        float s = ((redw[0] + redw[1]) + (redw[2] + redw[3]))
                + ((redw[4] + redw[5]) + (redw[6] + redw[7]));
        float w = ((i0 < HALF) == (j0 < HALF)) ? 1.0f : -1.0f;
        if (bi != bj) w *= 2.0f;
        atomicAdd(&g_acc, (double)(s * w));
    }
}

// ---------------------------------------------------------------------------
// k4: finalize mean (launch #5)
// ---------------------------------------------------------------------------
__global__ void k4_final(float* out) {
    if (threadIdx.x == 0)
        out[0] = (float)(g_acc / ((double)HALF * (double)HALF));
}

extern "C" void kernel_launch(void* const* d_in, const int* in_sizes, int n_in,
                              void* d_out, int out_size) {
    const float* src = (const float*)d_in[0];
    const float* tgt = (const float*)d_in[1];
    float* out = (float*)d_out;

    cudaFuncSetAttribute(k3_mma, cudaFuncAttributeMaxDynamicSharedMemorySize, DSM_BYTES);

    k0_zero<<<1, 256>>>();
    k1f<<<NROWS / 8, 256>>>(src, tgt);
    k2_bandwidth<<<1, 256>>>();
    k3_mma<<<NTILES, 256, DSM_BYTES>>>();
    k4_final<<<1, 32>>>(out);
}

// round 7
// speedup vs baseline: 1.8879x; 1.0031x over previous
#include <cuda_runtime.h>
#include <cuda_bf16.h>
#include <cstdint>

// ---------------- problem constants ----------------
#define NROWS 8192           // 2 * 4096
#define HALF  4096
#define DIM   256
#define PROWB 1024           // physical row bytes: [hi(512B) | lo(512B)]
#define KTILES 12            // logical K = 768 bf16, chunks of 64 (128B)
#define BM 128
#define BN 128
#define NSTAGE 3
#define NBLK 64
#define NTILES (NBLK * (NBLK + 1) / 2)   // 2080

#define STAGE_BYTES 32768    // A 16KB + B 16KB
#define DSM_BYTES (NSTAGE * STAGE_BYTES) // 96KB -> 2 CTAs/SM

// ---------------- device scratch ----------------
__device__ double g_S1;
__device__ float  g_colsum[DIM];
__device__ float  g_sq[NROWS];
__device__ float  g_negc;            // -log2(e)/(16*bandwidth)
__device__ double g_acc;
__device__ __align__(16) __nv_bfloat16 g_X[(size_t)NROWS * 512]; // [hi|lo]

__constant__ int c_secA[3] = {0, 0, 1};   // A sections: hi,hi,lo
__constant__ int c_secB[3] = {0, 1, 0};   // B sections: hi,lo,hi

// ---------------- PTX helpers (base ISA only) ----------------
__device__ __forceinline__ float ex2f(float x) {
    float y; asm("ex2.approx.f32 %0, %1;" : "=f"(y) : "f"(x)); return y;
}
__device__ __forceinline__ uint32_t smem_u32(const void* p) {
    uint32_t a;
    asm("{ .reg .u64 t; cvta.to.shared.u64 t, %1; cvt.u32.u64 %0, t; }" : "=r"(a) : "l"(p));
    return a;
}
__device__ __forceinline__ void cp16(uint32_t saddr, const void* g) {
    asm volatile("cp.async.cg.shared.global [%0], [%1], 16;" :: "r"(saddr), "l"(g));
}
#define CP_COMMIT() asm volatile("cp.async.commit_group;" ::: "memory")
#define CP_WAIT1()  asm volatile("cp.async.wait_group 1;" ::: "memory")

__device__ __forceinline__ void ldsm4(uint32_t* r, uint32_t addr) {
    asm volatile("ldmatrix.sync.aligned.m8n8.x4.shared.b16 {%0,%1,%2,%3}, [%4];"
        : "=r"(r[0]), "=r"(r[1]), "=r"(r[2]), "=r"(r[3]) : "r"(addr));
}
__device__ __forceinline__ void mma16816(float* c, const uint32_t* a,
                                         uint32_t b0, uint32_t b1) {
    asm volatile(
        "mma.sync.aligned.m16n8k16.row.col.f32.bf16.bf16.f32 "
        "{%0,%1,%2,%3}, {%4,%5,%6,%7}, {%8,%9}, {%0,%1,%2,%3};"
        : "+f"(c[0]), "+f"(c[1]), "+f"(c[2]), "+f"(c[3])
        : "r"(a[0]), "r"(a[1]), "r"(a[2]), "r"(a[3]), "r"(b0), "r"(b1));
}
__device__ __forceinline__ uint32_t pack_bf16(float x, float y) {
    __nv_bfloat162 t = __floats2bfloat162_rn(x, y);
    return *reinterpret_cast<uint32_t*>(&t);
}

// ---------------------------------------------------------------------------
// k0: zero accumulators (launch #1)
// ---------------------------------------------------------------------------
__global__ void k0_zero() {
    int tid = threadIdx.x;
    if (tid == 0) g_S1 = 0.0;
    if (tid < DIM) g_colsum[tid] = 0.0f;
}

// ---------------------------------------------------------------------------
// k1f: fused rowstats + hi/lo bf16 split (launch #2). One warp per row.
// ---------------------------------------------------------------------------
__global__ void k1f(const float* __restrict__ src,
                    const float* __restrict__ tgt) {
    __shared__ float cs[DIM];
    __shared__ float s1p[8];
    int tid = threadIdx.x, warp = tid >> 5, lane = tid & 31;
    cs[tid] = 0.0f;
    __syncthreads();

    int row = blockIdx.x * 8 + warp;
    const float* p = (row < HALF) ? (src + (size_t)row * DIM)
                                  : (tgt + (size_t)(row - HALF) * DIM);
    const float4* p4 = (const float4*)p;
    float4 v0 = p4[lane];
    float4 v1 = p4[lane + 32];

    float vv[8] = { v0.x, v0.y, v0.z, v0.w, v1.x, v1.y, v1.z, v1.w };
    float l[8];
    float ss = 0.0f;
    #pragma unroll
    for (int i = 0; i < 8; i++) {
        float h = __bfloat162float(__float2bfloat16(vv[i]));
        l[i] = vv[i] - h;
        ss = fmaf(vv[i], vv[i], ss);
    }
    #pragma unroll
    for (int o = 16; o; o >>= 1) ss += __shfl_xor_sync(0xffffffffu, ss, o);
    if (lane == 0) { g_sq[row] = ss; s1p[warp] = ss; }

    char* base = (char*)g_X + (size_t)row * PROWB + 8 * lane;
    uint2 hv0 = { pack_bf16(vv[0], vv[1]), pack_bf16(vv[2], vv[3]) };
    uint2 hv1 = { pack_bf16(vv[4], vv[5]), pack_bf16(vv[6], vv[7]) };
    uint2 lv0 = { pack_bf16(l[0], l[1]),  pack_bf16(l[2], l[3]) };
    uint2 lv1 = { pack_bf16(l[4], l[5]),  pack_bf16(l[6], l[7]) };
    *(uint2*)(base)       = hv0;
    *(uint2*)(base + 256) = hv1;
    *(uint2*)(base + 512) = lv0;
    *(uint2*)(base + 768) = lv1;

    int c0 = 4 * lane;
    atomicAdd(&cs[c0 + 0], v0.x); atomicAdd(&cs[c0 + 1], v0.y);
    atomicAdd(&cs[c0 + 2], v0.z); atomicAdd(&cs[c0 + 3], v0.w);
    atomicAdd(&cs[128 + c0 + 0], v1.x); atomicAdd(&cs[128 + c0 + 1], v1.y);
    atomicAdd(&cs[128 + c0 + 2], v1.z); atomicAdd(&cs[128 + c0 + 3], v1.w);
    __syncthreads();

    if (tid == 0) {
        double s = 0.0;
        #pragma unroll
        for (int w = 0; w < 8; w++) s += (double)s1p[w];
        atomicAdd(&g_S1, s);
    }
    atomicAdd(&g_colsum[tid], cs[tid]);
}

// ---------------------------------------------------------------------------
// k2: bandwidth closed form (launch #3)
// ---------------------------------------------------------------------------
__global__ void k2_bandwidth() {
    __shared__ float red[DIM];
    int tid = threadIdx.x;
    float c = g_colsum[tid];
    red[tid] = c * c;
    __syncthreads();
    for (int s = 128; s; s >>= 1) { if (tid < s) red[tid] += red[tid + s]; __syncthreads(); }
    if (tid == 0) {
        const double N = (double)NROWS;
        double sum_l2 = 2.0 * N * g_S1 - 2.0 * (double)red[0];
        double bw = sum_l2 / (N * N - N);
        bw = bw / 4.0;
        g_negc = (float)(-1.4426950408889634 / (16.0 * bw));
        g_acc = 0.0;
    }
}

// ---------------------------------------------------------------------------
// k3: block-triangular 128x128 Gram GEMM (mma.sync bf16) + fused RBF epilogue
//     (launch #4 -> profiled). 256 thr, 2x4 warps of 64x32, 3-stage cp.async,
//     2 CTAs/SM, ONE barrier per K-chunk.
//
// Single-sync proof: at iteration it, the top barrier means every warp has
// finished computing chunk it-1 (program order). issue_stage(it+2) writes
// buffer (it+2)%3 == (it-1)%3, whose readers are therefore done. wait_group(1)
// before the barrier completes this thread's group for chunk it; the barrier
// then makes ALL threads' chunk-it smem writes visible. No bottom sync needed.
// ---------------------------------------------------------------------------
__global__ void __launch_bounds__(256, 2) k3_mma() {
    extern __shared__ char dsm[];
    uint32_t smbase = smem_u32(dsm);

    __shared__ float sqic[BM];
    __shared__ float sqjc[BN];
    __shared__ float redw[8];

    int tid = threadIdx.x, wid = tid >> 5, lane = tid & 31;

    // linear block id -> upper-triangle (bi, bj), bj >= bi
    int t = blockIdx.x;
    int bi = 0;
    #pragma unroll 1
    while (t >= NBLK - bi) { t -= NBLK - bi; bi++; }
    int bj = bi + t;
    int i0 = bi * BM, j0 = bj * BN;

    const char* Ag = (const char*)g_X + (size_t)i0 * PROWB;
    const char* Bg = (const char*)g_X + (size_t)j0 * PROWB;

    int lrow = tid >> 3;          // 0..31
    int lq   = tid & 7;
    uint32_t lo0 = (uint32_t)(lrow * 128 + lq * 16);

    auto issue_stage = [&](int ck, int buf) {
        uint32_t smA = smbase + buf * STAGE_BYTES;
        uint32_t smB = smA + 16384;
        int grp = ck >> 2, sub = ck & 3;
        const char* ga = Ag + c_secA[grp] * 512 + sub * 128 + lq * 16;
        const char* gb = Bg + c_secB[grp] * 512 + sub * 128 + lq * 16;
        #pragma unroll
        for (int i = 0; i < 4; i++) {
            uint32_t o = lo0 + (uint32_t)(i * 32 * 128);
            uint32_t sw = o ^ ((o >> 3) & 0x70);
            cp16(smA + sw, ga + (size_t)(lrow + 32 * i) * PROWB);
            cp16(smB + sw, gb + (size_t)(lrow + 32 * i) * PROWB);
        }
    };

    issue_stage(0, 0); CP_COMMIT();
    issue_stage(1, 1); CP_COMMIT();

    float negc = g_negc;
    if (tid < 128) sqic[tid] = g_sq[i0 + tid] * negc;
    else           sqjc[tid - 128] = g_sq[j0 + tid - 128] * negc;

    // warp tiling: 2(m) x 4(n), warp tile 64x32
    int wm = wid >> 2, wn = wid & 3;

    uint32_t arow[4], av[4];
    #pragma unroll
    for (int tm = 0; tm < 4; tm++) {
        uint32_t o = (uint32_t)((wm * 64 + tm * 16 + (lane & 15)) * 128);
        arow[tm] = o; av[tm] = (o >> 3) & 0x70;
    }
    uint32_t brow[2], bv[2];
    #pragma unroll
    for (int tg = 0; tg < 2; tg++) {
        uint32_t o = (uint32_t)((wn * 32 + tg * 16 + (lane & 15)) * 128);
        brow[tg] = o; bv[tg] = (o >> 3) & 0x70;
    }
    uint32_t ksel = (uint32_t)(lane & 16);

    float acc[4][4][4];
    #pragma unroll
    for (int a = 0; a < 4; a++)
        #pragma unroll
        for (int b = 0; b < 4; b++)
            #pragma unroll
            for (int e = 0; e < 4; e++) acc[a][b][e] = 0.0f;

    int buf = 0, ldbuf = 2;
    for (int it = 0; it < KTILES; it++) {
        CP_WAIT1();
        __syncthreads();              // the only barrier per chunk

        int ld = it + NSTAGE - 1;
        if (ld < KTILES) issue_stage(ld, ldbuf);
        CP_COMMIT();

        uint32_t smA = smbase + buf * STAGE_BYTES;
        uint32_t smB = smA + 16384;

        #pragma unroll
        for (int ks = 0; ks < 4; ks++) {
            uint32_t kb = (uint32_t)(ks * 32) + ksel;
            uint32_t a[4][4], b[2][4];
            #pragma unroll
            for (int tm = 0; tm < 4; tm++)
                ldsm4(a[tm], smA + arow[tm] + (kb ^ av[tm]));
            #pragma unroll
            for (int tg = 0; tg < 2; tg++)
                ldsm4(b[tg], smB + brow[tg] + (kb ^ bv[tg]));
            #pragma unroll
            for (int tm = 0; tm < 4; tm++) {
                mma16816(acc[tm][0], a[tm], b[0][0], b[0][2]);
                mma16816(acc[tm][1], a[tm], b[0][1], b[0][3]);
                mma16816(acc[tm][2], a[tm], b[1][0], b[1][2]);
                mma16816(acc[tm][3], a[tm], b[1][1], b[1][3]);
            }
        }
        buf = (buf == NSTAGE - 1) ? 0 : buf + 1;
        ldbuf = (ldbuf == NSTAGE - 1) ? 0 : ldbuf + 1;
    }

    // fused RBF epilogue
    float twoc = -2.0f * negc;
    float tsum = 0.0f;
    #pragma unroll
    for (int tm = 0; tm < 4; tm++) {
        int mb = wm * 64 + tm * 16 + (lane >> 2);
        float si0 = sqic[mb], si8 = sqic[mb + 8];
        #pragma unroll
        for (int tn = 0; tn < 4; tn++) {
            int nb = wn * 32 + tn * 8 + (lane & 3) * 2;
            float sj0 = sqjc[nb], sj1 = sqjc[nb + 1];
            float* cc = acc[tm][tn];
            float base[4] = { si0 + sj0, si0 + sj1, si8 + sj0, si8 + sj1 };
            #pragma unroll
            for (int e = 0; e < 4; e++) {
                float arg = fmaf(cc[e], twoc, base[e]);
                float u = ex2f(arg);
                float u2 = u * u, u4 = u2 * u2, u8 = u4 * u4, u16 = u8 * u8;
                tsum += ((u + u2) + (u4 + u8)) + u16;
            }
        }
    }
    #pragma unroll
    for (int o = 16; o; o >>= 1) tsum += __shfl_xor_sync(0xffffffffu, tsum, o);
    if (lane == 0) redw[wid] = tsum;
    __syncthreads();
    if (tid == 0) {
        float s = ((redw[0] + redw[1]) + (redw[2] + redw[3]))
                + ((redw[4] + redw[5]) + (redw[6] + redw[7]));
        float w = ((i0 < HALF) == (j0 < HALF)) ? 1.0f : -1.0f;
        if (bi != bj) w *= 2.0f;
        atomicAdd(&g_acc, (double)(s * w));
    }
}

// ---------------------------------------------------------------------------
// k4: finalize mean (launch #5)
// ---------------------------------------------------------------------------
__global__ void k4_final(float* out) {
    if (threadIdx.x == 0)
        out[0] = (float)(g_acc / ((double)HALF * (double)HALF));
}

extern "C" void kernel_launch(void* const* d_in, const int* in_sizes, int n_in,
                              void* d_out, int out_size) {
    const float* src = (const float*)d_in[0];
    const float* tgt = (const float*)d_in[1];
    float* out = (float*)d_out;

    cudaFuncSetAttribute(k3_mma, cudaFuncAttributeMaxDynamicSharedMemorySize, DSM_BYTES);

    k0_zero<<<1, 256>>>();
    k1f<<<NROWS / 8, 256>>>(src, tgt);
    k2_bandwidth<<<1, 256>>>();
    k3_mma<<<NTILES, 256, DSM_BYTES>>>();
    k4_final<<<1, 32>>>(out);
}

// round 8
// speedup vs baseline: 1.8883x; 1.0002x over previous
#include <cuda_runtime.h>
#include <cuda_bf16.h>
#include <cstdint>

// ---------------- problem constants ----------------
#define NROWS 8192           // 2 * 4096
#define HALF  4096
#define DIM   256
#define PROWB 1024           // physical row bytes: [hi(512B) | lo(512B)]
#define KTILES 12            // logical K = 768 bf16, chunks of 64 (128B)
#define BM 128
#define BN 128
#define NSTAGE 3
#define NBLK 64
#define NTILES (NBLK * (NBLK + 1) / 2)   // 2080
#define THREADS 512

#define STAGE_BYTES 32768    // A 16KB + B 16KB
#define DSM_BYTES (NSTAGE * STAGE_BYTES) // 96KB -> 2 CTAs/SM

// ---------------- device scratch ----------------
__device__ double g_S1;
__device__ float  g_colsum[DIM];
__device__ float  g_sq[NROWS];
__device__ float  g_negc;            // -log2(e)/(16*bandwidth)
__device__ double g_acc;
__device__ __align__(16) __nv_bfloat16 g_X[(size_t)NROWS * 512]; // [hi|lo]

__constant__ int c_secA[3] = {0, 0, 1};   // A sections: hi,hi,lo
__constant__ int c_secB[3] = {0, 1, 0};   // B sections: hi,lo,hi

// ---------------- PTX helpers (base ISA only) ----------------
__device__ __forceinline__ float ex2f(float x) {
    float y; asm("ex2.approx.f32 %0, %1;" : "=f"(y) : "f"(x)); return y;
}
__device__ __forceinline__ uint32_t smem_u32(const void* p) {
    uint32_t a;
    asm("{ .reg .u64 t; cvta.to.shared.u64 t, %1; cvt.u32.u64 %0, t; }" : "=r"(a) : "l"(p));
    return a;
}
__device__ __forceinline__ void cp16(uint32_t saddr, const void* g) {
    asm volatile("cp.async.cg.shared.global [%0], [%1], 16;" :: "r"(saddr), "l"(g));
}
#define CP_COMMIT() asm volatile("cp.async.commit_group;" ::: "memory")
#define CP_WAIT1()  asm volatile("cp.async.wait_group 1;" ::: "memory")

__device__ __forceinline__ void ldsm4(uint32_t* r, uint32_t addr) {
    asm volatile("ldmatrix.sync.aligned.m8n8.x4.shared.b16 {%0,%1,%2,%3}, [%4];"
        : "=r"(r[0]), "=r"(r[1]), "=r"(r[2]), "=r"(r[3]) : "r"(addr));
}
__device__ __forceinline__ void mma16816(float* c, const uint32_t* a,
                                         uint32_t b0, uint32_t b1) {
    asm volatile(
        "mma.sync.aligned.m16n8k16.row.col.f32.bf16.bf16.f32 "
        "{%0,%1,%2,%3}, {%4,%5,%6,%7}, {%8,%9}, {%0,%1,%2,%3};"
        : "+f"(c[0]), "+f"(c[1]), "+f"(c[2]), "+f"(c[3])
        : "r"(a[0]), "r"(a[1]), "r"(a[2]), "r"(a[3]), "r"(b0), "r"(b1));
}
__device__ __forceinline__ uint32_t pack_bf16(float x, float y) {
    __nv_bfloat162 t = __floats2bfloat162_rn(x, y);
    return *reinterpret_cast<uint32_t*>(&t);
}

// ---------------------------------------------------------------------------
// k0: zero accumulators (launch #1)
// ---------------------------------------------------------------------------
__global__ void k0_zero() {
    int tid = threadIdx.x;
    if (tid == 0) g_S1 = 0.0;
    if (tid < DIM) g_colsum[tid] = 0.0f;
}

// ---------------------------------------------------------------------------
// k1f: fused rowstats + hi/lo bf16 split (launch #2). One warp per row.
// ---------------------------------------------------------------------------
__global__ void k1f(const float* __restrict__ src,
                    const float* __restrict__ tgt) {
    __shared__ float cs[DIM];
    __shared__ float s1p[8];
    int tid = threadIdx.x, warp = tid >> 5, lane = tid & 31;
    cs[tid] = 0.0f;
    __syncthreads();

    int row = blockIdx.x * 8 + warp;
    const float* p = (row < HALF) ? (src + (size_t)row * DIM)
                                  : (tgt + (size_t)(row - HALF) * DIM);
    const float4* p4 = (const float4*)p;
    float4 v0 = p4[lane];
    float4 v1 = p4[lane + 32];

    float vv[8] = { v0.x, v0.y, v0.z, v0.w, v1.x, v1.y, v1.z, v1.w };
    float l[8];
    float ss = 0.0f;
    #pragma unroll
    for (int i = 0; i < 8; i++) {
        float h = __bfloat162float(__float2bfloat16(vv[i]));
        l[i] = vv[i] - h;
        ss = fmaf(vv[i], vv[i], ss);
    }
    #pragma unroll
    for (int o = 16; o; o >>= 1) ss += __shfl_xor_sync(0xffffffffu, ss, o);
    if (lane == 0) { g_sq[row] = ss; s1p[warp] = ss; }

    char* base = (char*)g_X + (size_t)row * PROWB + 8 * lane;
    uint2 hv0 = { pack_bf16(vv[0], vv[1]), pack_bf16(vv[2], vv[3]) };
    uint2 hv1 = { pack_bf16(vv[4], vv[5]), pack_bf16(vv[6], vv[7]) };
    uint2 lv0 = { pack_bf16(l[0], l[1]),  pack_bf16(l[2], l[3]) };
    uint2 lv1 = { pack_bf16(l[4], l[5]),  pack_bf16(l[6], l[7]) };
    *(uint2*)(base)       = hv0;
    *(uint2*)(base + 256) = hv1;
    *(uint2*)(base + 512) = lv0;
    *(uint2*)(base + 768) = lv1;

    int c0 = 4 * lane;
    atomicAdd(&cs[c0 + 0], v0.x); atomicAdd(&cs[c0 + 1], v0.y);
    atomicAdd(&cs[c0 + 2], v0.z); atomicAdd(&cs[c0 + 3], v0.w);
    atomicAdd(&cs[128 + c0 + 0], v1.x); atomicAdd(&cs[128 + c0 + 1], v1.y);
    atomicAdd(&cs[128 + c0 + 2], v1.z); atomicAdd(&cs[128 + c0 + 3], v1.w);
    __syncthreads();

    if (tid == 0) {
        double s = 0.0;
        #pragma unroll
        for (int w = 0; w < 8; w++) s += (double)s1p[w];
        atomicAdd(&g_S1, s);
    }
    atomicAdd(&g_colsum[tid], cs[tid]);
}

// ---------------------------------------------------------------------------
// k2: bandwidth closed form (launch #3)
// ---------------------------------------------------------------------------
__global__ void k2_bandwidth() {
    __shared__ float red[DIM];
    int tid = threadIdx.x;
    float c = g_colsum[tid];
    red[tid] = c * c;
    __syncthreads();
    for (int s = 128; s; s >>= 1) { if (tid < s) red[tid] += red[tid + s]; __syncthreads(); }
    if (tid == 0) {
        const double N = (double)NROWS;
        double sum_l2 = 2.0 * N * g_S1 - 2.0 * (double)red[0];
        double bw = sum_l2 / (N * N - N);
        bw = bw / 4.0;
        g_negc = (float)(-1.4426950408889634 / (16.0 * bw));
        g_acc = 0.0;
    }
}

// ---------------------------------------------------------------------------
// k3: block-triangular 128x128 Gram GEMM (mma.sync bf16) + fused RBF epilogue
//     (launch #4 -> profiled). 512 thr, 4x4 warps of 32x32 tiles,
//     3-stage cp.async, 2 CTAs/SM (32 warps/SM, 8 per SMSP).
// ---------------------------------------------------------------------------
__global__ void __launch_bounds__(THREADS, 2) k3_mma() {
    extern __shared__ char dsm[];
    uint32_t smbase = smem_u32(dsm);

    __shared__ float sqic[BM];
    __shared__ float sqjc[BN];
    __shared__ float redw[16];

    int tid = threadIdx.x, wid = tid >> 5, lane = tid & 31;

    // linear block id -> upper-triangle (bi, bj), bj >= bi
    int t = blockIdx.x;
    int bi = 0;
    #pragma unroll 1
    while (t >= NBLK - bi) { t -= NBLK - bi; bi++; }
    int bj = bi + t;
    int i0 = bi * BM, j0 = bj * BN;

    const char* Ag = (const char*)g_X + (size_t)i0 * PROWB;
    const char* Bg = (const char*)g_X + (size_t)j0 * PROWB;

    // loader: 512 threads; 4 threads per row, each does chunks lq and lq+4
    int lrow = tid >> 2;          // 0..127
    int lq   = tid & 3;           // 16B chunk pair base
    uint32_t lo1 = (uint32_t)(lrow * 128 + lq * 16);
    uint32_t lo2 = lo1 + 64;
    uint32_t sw1 = lo1 ^ ((lo1 >> 3) & 0x70);
    uint32_t sw2 = lo2 ^ ((lo2 >> 3) & 0x70);

    auto issue_stage = [&](int ck, int buf) {
        uint32_t smA = smbase + buf * STAGE_BYTES;
        uint32_t smB = smA + 16384;
        int grp = ck >> 2, sub = ck & 3;
        const char* ga = Ag + (size_t)lrow * PROWB + c_secA[grp] * 512 + sub * 128;
        const char* gb = Bg + (size_t)lrow * PROWB + c_secB[grp] * 512 + sub * 128;
        cp16(smA + sw1, ga + lq * 16);
        cp16(smA + sw2, ga + lq * 16 + 64);
        cp16(smB + sw1, gb + lq * 16);
        cp16(smB + sw2, gb + lq * 16 + 64);
    };

    issue_stage(0, 0); CP_COMMIT();
    issue_stage(1, 1); CP_COMMIT();

    float negc = g_negc;
    if (tid < 128)                 sqic[tid]       = g_sq[i0 + tid] * negc;
    else if (tid < 256)            sqjc[tid - 128] = g_sq[j0 + tid - 128] * negc;

    // warp tiling: 4(m) x 4(n), warp tile 32x32
    int wm = wid >> 2, wn = wid & 3;

    uint32_t arow[2], av[2];
    #pragma unroll
    for (int tm = 0; tm < 2; tm++) {
        uint32_t o = (uint32_t)((wm * 32 + tm * 16 + (lane & 15)) * 128);
        arow[tm] = o; av[tm] = (o >> 3) & 0x70;
    }
    uint32_t brow[2], bv[2];
    #pragma unroll
    for (int tg = 0; tg < 2; tg++) {
        uint32_t o = (uint32_t)((wn * 32 + tg * 16 + (lane & 15)) * 128);
        brow[tg] = o; bv[tg] = (o >> 3) & 0x70;
    }
    uint32_t ksel = (uint32_t)(lane & 16);

    float acc[2][4][4];
    #pragma unroll
    for (int a = 0; a < 2; a++)
        #pragma unroll
        for (int b = 0; b < 4; b++)
            #pragma unroll
            for (int e = 0; e < 4; e++) acc[a][b][e] = 0.0f;

    int buf = 0, ldbuf = 2;
    for (int it = 0; it < KTILES; it++) {
        CP_WAIT1();
        __syncthreads();

        int ld = it + NSTAGE - 1;
        if (ld < KTILES) issue_stage(ld, ldbuf);
        CP_COMMIT();

        uint32_t smA = smbase + buf * STAGE_BYTES;
        uint32_t smB = smA + 16384;

        #pragma unroll
        for (int ks = 0; ks < 4; ks++) {
            uint32_t kb = (uint32_t)(ks * 32) + ksel;
            uint32_t a[2][4], b[2][4];
            #pragma unroll
            for (int tm = 0; tm < 2; tm++)
                ldsm4(a[tm], smA + arow[tm] + (kb ^ av[tm]));
            #pragma unroll
            for (int tg = 0; tg < 2; tg++)
                ldsm4(b[tg], smB + brow[tg] + (kb ^ bv[tg]));
            #pragma unroll
            for (int tm = 0; tm < 2; tm++) {
                mma16816(acc[tm][0], a[tm], b[0][0], b[0][2]);
                mma16816(acc[tm][1], a[tm], b[0][1], b[0][3]);
                mma16816(acc[tm][2], a[tm], b[1][0], b[1][2]);
                mma16816(acc[tm][3], a[tm], b[1][1], b[1][3]);
            }
        }
        buf = (buf == NSTAGE - 1) ? 0 : buf + 1;
        ldbuf = (ldbuf == NSTAGE - 1) ? 0 : ldbuf + 1;
    }

    // fused RBF epilogue
    float twoc = -2.0f * negc;
    float tsum = 0.0f;
    #pragma unroll
    for (int tm = 0; tm < 2; tm++) {
        int mb = wm * 32 + tm * 16 + (lane >> 2);
        float si0 = sqic[mb], si8 = sqic[mb + 8];
        #pragma unroll
        for (int tn = 0; tn < 4; tn++) {
            int nb = wn * 32 + tn * 8 + (lane & 3) * 2;
            float sj0 = sqjc[nb], sj1 = sqjc[nb + 1];
            float* cc = acc[tm][tn];
            float base[4] = { si0 + sj0, si0 + sj1, si8 + sj0, si8 + sj1 };
            #pragma unroll
            for (int e = 0; e < 4; e++) {
                float arg = fmaf(cc[e], twoc, base[e]);
                float u = ex2f(arg);
                float u2 = u * u, u4 = u2 * u2, u8 = u4 * u4, u16 = u8 * u8;
                tsum += ((u + u2) + (u4 + u8)) + u16;
            }
        }
    }
    #pragma unroll
    for (int o = 16; o; o >>= 1) tsum += __shfl_xor_sync(0xffffffffu, tsum, o);
    if (lane == 0) redw[wid] = tsum;
    __syncthreads();
    if (tid == 0) {
        float s = 0.0f;
        #pragma unroll
        for (int w = 0; w < 16; w++) s += redw[w];
        float wgt = ((i0 < HALF) == (j0 < HALF)) ? 1.0f : -1.0f;
        if (bi != bj) wgt *= 2.0f;
        atomicAdd(&g_acc, (double)(s * wgt));
    }
}

// ---------------------------------------------------------------------------
// k4: finalize mean (launch #5)
// ---------------------------------------------------------------------------
__global__ void k4_final(float* out) {
    if (threadIdx.x == 0)
        out[0] = (float)(g_acc / ((double)HALF * (double)HALF));
}

extern "C" void kernel_launch(void* const* d_in, const int* in_sizes, int n_in,
                              void* d_out, int out_size) {
    const float* src = (const float*)d_in[0];
    const float* tgt = (const float*)d_in[1];
    float* out = (float*)d_out;

    cudaFuncSetAttribute(k3_mma, cudaFuncAttributeMaxDynamicSharedMemorySize, DSM_BYTES);

    k0_zero<<<1, 256>>>();
    k1f<<<NROWS / 8, 256>>>(src, tgt);
    k2_bandwidth<<<1, 256>>>();
    k3_mma<<<NTILES, THREADS, DSM_BYTES>>>();
    k4_final<<<1, 32>>>(out);
}

// round 10
// speedup vs baseline: 1.9025x; 1.0075x over previous
#include <cuda_runtime.h>
#include <cuda_bf16.h>
#include <cstdint>

// ---------------- problem constants ----------------
#define NROWS 8192           // 2 * 4096
#define HALF  4096
#define DIM   256
#define PROWB 1024           // physical row bytes: [hi(512B) | lo(512B)]
#define KTILES 12            // logical K = 768 bf16, chunks of 64 (128B)
#define BM 128
#define BN 128
#define NSTAGE 3
#define NBLK 64
#define NTILES (NBLK * (NBLK + 1) / 2)   // 2080

#define STAGE_BYTES 32768    // A 16KB + B 16KB
#define DSM_BYTES (NSTAGE * STAGE_BYTES) // 96KB -> 2 CTAs/SM

// ---------------- device scratch ----------------
__device__ double g_S1;
__device__ float  g_colsum[DIM];
__device__ float  g_sq[NROWS];
__device__ float  g_negc;            // -log2(e)/(16*bandwidth)
__device__ double g_acc;
__device__ __align__(16) __nv_bfloat16 g_X[(size_t)NROWS * 512]; // [hi|lo]

__constant__ int c_secA[3] = {0, 0, 1};   // A sections: hi,hi,lo
__constant__ int c_secB[3] = {0, 1, 0};   // B sections: hi,lo,hi

// ---------------- PTX helpers (base ISA only) ----------------
__device__ __forceinline__ float ex2f(float x) {
    float y; asm("ex2.approx.f32 %0, %1;" : "=f"(y) : "f"(x)); return y;
}
__device__ __forceinline__ uint32_t smem_u32(const void* p) {
    uint32_t a;
    asm("{ .reg .u64 t; cvta.to.shared.u64 t, %1; cvt.u32.u64 %0, t; }" : "=r"(a) : "l"(p));
    return a;
}
__device__ __forceinline__ void cp16(uint32_t saddr, const void* g) {
    asm volatile("cp.async.cg.shared.global [%0], [%1], 16;" :: "r"(saddr), "l"(g));
}
#define CP_COMMIT() asm volatile("cp.async.commit_group;" ::: "memory")
#define CP_WAIT1()  asm volatile("cp.async.wait_group 1;" ::: "memory")

__device__ __forceinline__ void ldsm4(uint32_t* r, uint32_t addr) {
    asm volatile("ldmatrix.sync.aligned.m8n8.x4.shared.b16 {%0,%1,%2,%3}, [%4];"
        : "=r"(r[0]), "=r"(r[1]), "=r"(r[2]), "=r"(r[3]) : "r"(addr));
}
__device__ __forceinline__ void mma16816(float* c, const uint32_t* a,
                                         uint32_t b0, uint32_t b1) {
    asm volatile(
        "mma.sync.aligned.m16n8k16.row.col.f32.bf16.bf16.f32 "
        "{%0,%1,%2,%3}, {%4,%5,%6,%7}, {%8,%9}, {%0,%1,%2,%3};"
        : "+f"(c[0]), "+f"(c[1]), "+f"(c[2]), "+f"(c[3])
        : "r"(a[0]), "r"(a[1]), "r"(a[2]), "r"(a[3]), "r"(b0), "r"(b1));
}
__device__ __forceinline__ uint32_t pack_bf16(float x, float y) {
    __nv_bfloat162 t = __floats2bfloat162_rn(x, y);
    return *reinterpret_cast<uint32_t*>(&t);
}

// ---------------------------------------------------------------------------
// k0: zero accumulators (launch #1)
// ---------------------------------------------------------------------------
__global__ void k0_zero() {
    int tid = threadIdx.x;
    if (tid == 0) g_S1 = 0.0;
    if (tid < DIM) g_colsum[tid] = 0.0f;
}

// ---------------------------------------------------------------------------
// k1f: fused rowstats + hi/lo bf16 split (launch #2). One warp per row.
// ---------------------------------------------------------------------------
__global__ void k1f(const float* __restrict__ src,
                    const float* __restrict__ tgt) {
    __shared__ float cs[DIM];
    __shared__ float s1p[8];
    int tid = threadIdx.x, warp = tid >> 5, lane = tid & 31;
    cs[tid] = 0.0f;
    __syncthreads();

    int row = blockIdx.x * 8 + warp;
    const float* p = (row < HALF) ? (src + (size_t)row * DIM)
                                  : (tgt + (size_t)(row - HALF) * DIM);
    const float4* p4 = (const float4*)p;
    float4 v0 = p4[lane];
    float4 v1 = p4[lane + 32];

    float vv[8] = { v0.x, v0.y, v0.z, v0.w, v1.x, v1.y, v1.z, v1.w };
    float l[8];
    float ss = 0.0f;
    #pragma unroll
    for (int i = 0; i < 8; i++) {
        float h = __bfloat162float(__float2bfloat16(vv[i]));
        l[i] = vv[i] - h;
        ss = fmaf(vv[i], vv[i], ss);
    }
    #pragma unroll
    for (int o = 16; o; o >>= 1) ss += __shfl_xor_sync(0xffffffffu, ss, o);
    if (lane == 0) { g_sq[row] = ss; s1p[warp] = ss; }

    char* base = (char*)g_X + (size_t)row * PROWB + 8 * lane;
    uint2 hv0 = { pack_bf16(vv[0], vv[1]), pack_bf16(vv[2], vv[3]) };
    uint2 hv1 = { pack_bf16(vv[4], vv[5]), pack_bf16(vv[6], vv[7]) };
    uint2 lv0 = { pack_bf16(l[0], l[1]),  pack_bf16(l[2], l[3]) };
    uint2 lv1 = { pack_bf16(l[4], l[5]),  pack_bf16(l[6], l[7]) };
    *(uint2*)(base)       = hv0;
    *(uint2*)(base + 256) = hv1;
    *(uint2*)(base + 512) = lv0;
    *(uint2*)(base + 768) = lv1;

    int c0 = 4 * lane;
    atomicAdd(&cs[c0 + 0], v0.x); atomicAdd(&cs[c0 + 1], v0.y);
    atomicAdd(&cs[c0 + 2], v0.z); atomicAdd(&cs[c0 + 3], v0.w);
    atomicAdd(&cs[128 + c0 + 0], v1.x); atomicAdd(&cs[128 + c0 + 1], v1.y);
    atomicAdd(&cs[128 + c0 + 2], v1.z); atomicAdd(&cs[128 + c0 + 3], v1.w);
    __syncthreads();

    if (tid == 0) {
        double s = 0.0;
        #pragma unroll
        for (int w = 0; w < 8; w++) s += (double)s1p[w];
        atomicAdd(&g_S1, s);
    }
    atomicAdd(&g_colsum[tid], cs[tid]);
}

// ---------------------------------------------------------------------------
// k2: bandwidth closed form (launch #3)
// ---------------------------------------------------------------------------
__global__ void k2_bandwidth() {
    __shared__ float red[DIM];
    int tid = threadIdx.x;
    float c = g_colsum[tid];
    red[tid] = c * c;
    __syncthreads();
    for (int s = 128; s; s >>= 1) { if (tid < s) red[tid] += red[tid + s]; __syncthreads(); }
    if (tid == 0) {
        const double N = (double)NROWS;
        double sum_l2 = 2.0 * N * g_S1 - 2.0 * (double)red[0];
        double bw = sum_l2 / (N * N - N);
        bw = bw / 4.0;
        g_negc = (float)(-1.4426950408889634 / (16.0 * bw));
        g_acc = 0.0;
    }
}

// ---------------------------------------------------------------------------
// k3: block-triangular 128x128 Gram GEMM (mma.sync bf16) + fused RBF epilogue
//     (launch #4 -> profiled). 256 thr, 2x4 warps of 64x32, 3-stage cp.async,
//     2 CTAs/SM, intra-chunk ldsm/mma double-buffer pipeline.
// ---------------------------------------------------------------------------
__global__ void __launch_bounds__(256, 2) k3_mma() {
    extern __shared__ char dsm[];
    uint32_t smbase = smem_u32(dsm);

    __shared__ float sqic[BM];
    __shared__ float sqjc[BN];
    __shared__ float redw[8];

    int tid = threadIdx.x, wid = tid >> 5, lane = tid & 31;

    // linear block id -> upper-triangle (bi, bj), bj >= bi
    int t = blockIdx.x;
    int bi = 0;
    #pragma unroll 1
    while (t >= NBLK - bi) { t -= NBLK - bi; bi++; }
    int bj = bi + t;
    int i0 = bi * BM, j0 = bj * BN;

    const char* Ag = (const char*)g_X + (size_t)i0 * PROWB;
    const char* Bg = (const char*)g_X + (size_t)j0 * PROWB;

    int lrow = tid >> 3;          // 0..31
    int lq   = tid & 7;
    uint32_t lo0 = (uint32_t)(lrow * 128 + lq * 16);

    auto issue_stage = [&](int ck, int buf) {
        uint32_t smA = smbase + buf * STAGE_BYTES;
        uint32_t smB = smA + 16384;
        int grp = ck >> 2, sub = ck & 3;
        const char* ga = Ag + c_secA[grp] * 512 + sub * 128 + lq * 16;
        const char* gb = Bg + c_secB[grp] * 512 + sub * 128 + lq * 16;
        #pragma unroll
        for (int i = 0; i < 4; i++) {
            uint32_t o = lo0 + (uint32_t)(i * 32 * 128);
            uint32_t sw = o ^ ((o >> 3) & 0x70);
            cp16(smA + sw, ga + (size_t)(lrow + 32 * i) * PROWB);
            cp16(smB + sw, gb + (size_t)(lrow + 32 * i) * PROWB);
        }
    };

    issue_stage(0, 0); CP_COMMIT();
    issue_stage(1, 1); CP_COMMIT();

    float negc = g_negc;
    if (tid < 128) sqic[tid] = g_sq[i0 + tid] * negc;
    else           sqjc[tid - 128] = g_sq[j0 + tid - 128] * negc;

    // warp tiling: 2(m) x 4(n), warp tile 64x32
    int wm = wid >> 2, wn = wid & 3;

    uint32_t arow[4], av[4];
    #pragma unroll
    for (int tm = 0; tm < 4; tm++) {
        uint32_t o = (uint32_t)((wm * 64 + tm * 16 + (lane & 15)) * 128);
        arow[tm] = o; av[tm] = (o >> 3) & 0x70;
    }
    uint32_t brow[2], bv[2];
    #pragma unroll
    for (int tg = 0; tg < 2; tg++) {
        uint32_t o = (uint32_t)((wn * 32 + tg * 16 + (lane & 15)) * 128);
        brow[tg] = o; bv[tg] = (o >> 3) & 0x70;
    }
    uint32_t ksel = (uint32_t)(lane & 16);

    float acc[4][4][4];
    #pragma unroll
    for (int a = 0; a < 4; a++)
        #pragma unroll
        for (int b = 0; b < 4; b++)
            #pragma unroll
            for (int e = 0; e < 4; e++) acc[a][b][e] = 0.0f;

    // fragment double buffers
    uint32_t afr[2][4][4], bfr[2][2][4];

    auto ld_frags = [&](uint32_t smA, uint32_t smB, int ks, int pb) {
        uint32_t kb = (uint32_t)(ks * 32) + ksel;
        #pragma unroll
        for (int tm = 0; tm < 4; tm++)
            ldsm4(afr[pb][tm], smA + arow[tm] + (kb ^ av[tm]));
        #pragma unroll
        for (int tg = 0; tg < 2; tg++)
            ldsm4(bfr[pb][tg], smB + brow[tg] + (kb ^ bv[tg]));
    };
    auto mma_all = [&](int pb) {
        #pragma unroll
        for (int tm = 0; tm < 4; tm++) {
            mma16816(acc[tm][0], afr[pb][tm], bfr[pb][0][0], bfr[pb][0][2]);
            mma16816(acc[tm][1], afr[pb][tm], bfr[pb][0][1], bfr[pb][0][3]);
            mma16816(acc[tm][2], afr[pb][tm], bfr[pb][1][0], bfr[pb][1][2]);
            mma16816(acc[tm][3], afr[pb][tm], bfr[pb][1][1], bfr[pb][1][3]);
        }
    };

    int buf = 0, ldbuf = 2;
    for (int it = 0; it < KTILES; it++) {
        CP_WAIT1();
        __syncthreads();

        uint32_t smA = smbase + buf * STAGE_BYTES;
        uint32_t smB = smA + 16384;

        ld_frags(smA, smB, 0, 0);            // prime ks=0

        int ld = it + NSTAGE - 1;
        if (ld < KTILES) issue_stage(ld, ldbuf);
        CP_COMMIT();

        ld_frags(smA, smB, 1, 1);  mma_all(0);   // ks=0 compute, ks=1 load
        ld_frags(smA, smB, 2, 0);  mma_all(1);   // ks=1 compute, ks=2 load
        ld_frags(smA, smB, 3, 1);  mma_all(0);   // ks=2 compute, ks=3 load
        mma_all(1);                               // ks=3 compute

        buf = (buf == NSTAGE - 1) ? 0 : buf + 1;
        ldbuf = (ldbuf == NSTAGE - 1) ? 0 : ldbuf + 1;
    }

    // fused RBF epilogue
    float twoc = -2.0f * negc;
    float tsum = 0.0f;
    #pragma unroll
    for (int tm = 0; tm < 4; tm++) {
        int mb = wm * 64 + tm * 16 + (lane >> 2);
        float si0 = sqic[mb], si8 = sqic[mb + 8];
        #pragma unroll
        for (int tn = 0; tn < 4; tn++) {
            int nb = wn * 32 + tn * 8 + (lane & 3) * 2;
            float sj0 = sqjc[nb], sj1 = sqjc[nb + 1];
            float* cc = acc[tm][tn];
            float base[4] = { si0 + sj0, si0 + sj1, si8 + sj0, si8 + sj1 };
            #pragma unroll
            for (int e = 0; e < 4; e++) {
                float arg = fmaf(cc[e], twoc, base[e]);
                float u = ex2f(arg);
                float u2 = u * u, u4 = u2 * u2, u8 = u4 * u4, u16 = u8 * u8;
                tsum += ((u + u2) + (u4 + u8)) + u16;
            }
        }
    }
    #pragma unroll
    for (int o = 16; o; o >>= 1) tsum += __shfl_xor_sync(0xffffffffu, tsum, o);
    if (lane == 0) redw[wid] = tsum;
    __syncthreads();
    if (tid == 0) {
        float s = ((redw[0] + redw[1]) + (redw[2] + redw[3]))
                + ((redw[4] + redw[5]) + (redw[6] + redw[7]));
        float w = ((i0 < HALF) == (j0 < HALF)) ? 1.0f : -1.0f;
        if (bi != bj) w *= 2.0f;
        atomicAdd(&g_acc, (double)(s * w));
    }
}

// ---------------------------------------------------------------------------
// k4: finalize mean (launch #5)
// ---------------------------------------------------------------------------
__global__ void k4_final(float* out) {
    if (threadIdx.x == 0)
        out[0] = (float)(g_acc / ((double)HALF * (double)HALF));
}

extern "C" void kernel_launch(void* const* d_in, const int* in_sizes, int n_in,
                              void* d_out, int out_size) {
    const float* src = (const float*)d_in[0];
    const float* tgt = (const float*)d_in[1];
    float* out = (float*)d_out;

    cudaFuncSetAttribute(k3_mma, cudaFuncAttributeMaxDynamicSharedMemorySize, DSM_BYTES);

    k0_zero<<<1, 256>>>();
    k1f<<<NROWS / 8, 256>>>(src, tgt);
    k2_bandwidth<<<1, 256>>>();
    k3_mma<<<NTILES, 256, DSM_BYTES>>>();
    k4_final<<<1, 32>>>(out);
}

// round 11
// speedup vs baseline: 3.8730x; 2.0358x over previous
#include <cuda_runtime.h>
#include <cuda_fp16.h>
#include <cstdint>

// ---------------- problem constants ----------------
#define NROWS 8192           // 2 * 4096
#define HALF  4096
#define DIM   256
#define PROWB 512            // physical row bytes: 256 fp16
#define KTILES 4             // K = 256 fp16, chunks of 64 (128B)
#define BM 128
#define BN 128
#define NSTAGE 3
#define NBLK 64
#define NTILES (NBLK * (NBLK + 1) / 2)   // 2080

#define STAGE_BYTES 32768    // A 16KB + B 16KB
#define DSM_BYTES (NSTAGE * STAGE_BYTES) // 96KB -> 2 CTAs/SM

// ---------------- device scratch ----------------
__device__ double g_S1;
__device__ float  g_colsum[DIM];
__device__ float  g_sq[NROWS];
__device__ float  g_negc;            // -log2(e)/(16*bandwidth)
__device__ double g_acc;
__device__ __align__(16) __half g_X[(size_t)NROWS * DIM];  // fp16 rows (4MB, L2-resident)

// ---------------- PTX helpers (base ISA only) ----------------
__device__ __forceinline__ float ex2f(float x) {
    float y; asm("ex2.approx.f32 %0, %1;" : "=f"(y) : "f"(x)); return y;
}
__device__ __forceinline__ uint32_t smem_u32(const void* p) {
    uint32_t a;
    asm("{ .reg .u64 t; cvta.to.shared.u64 t, %1; cvt.u32.u64 %0, t; }" : "=r"(a) : "l"(p));
    return a;
}
__device__ __forceinline__ void cp16(uint32_t saddr, const void* g) {
    asm volatile("cp.async.cg.shared.global [%0], [%1], 16;" :: "r"(saddr), "l"(g));
}
#define CP_COMMIT() asm volatile("cp.async.commit_group;" ::: "memory")
#define CP_WAIT1()  asm volatile("cp.async.wait_group 1;" ::: "memory")

__device__ __forceinline__ void ldsm4(uint32_t* r, uint32_t addr) {
    asm volatile("ldmatrix.sync.aligned.m8n8.x4.shared.b16 {%0,%1,%2,%3}, [%4];"
        : "=r"(r[0]), "=r"(r[1]), "=r"(r[2]), "=r"(r[3]) : "r"(addr));
}
__device__ __forceinline__ void mma16816(float* c, const uint32_t* a,
                                         uint32_t b0, uint32_t b1) {
    asm volatile(
        "mma.sync.aligned.m16n8k16.row.col.f32.f16.f16.f32 "
        "{%0,%1,%2,%3}, {%4,%5,%6,%7}, {%8,%9}, {%0,%1,%2,%3};"
        : "+f"(c[0]), "+f"(c[1]), "+f"(c[2]), "+f"(c[3])
        : "r"(a[0]), "r"(a[1]), "r"(a[2]), "r"(a[3]), "r"(b0), "r"(b1));
}
__device__ __forceinline__ uint32_t pack_h2(float x, float y) {
    __half2 t = __floats2half2_rn(x, y);
    return *reinterpret_cast<uint32_t*>(&t);
}

// ---------------------------------------------------------------------------
// k0: zero accumulators (launch #1)
// ---------------------------------------------------------------------------
__global__ void k0_zero() {
    int tid = threadIdx.x;
    if (tid == 0) g_S1 = 0.0;
    if (tid < DIM) g_colsum[tid] = 0.0f;
}

// ---------------------------------------------------------------------------
// k1f: fused rowstats + fp16 convert (launch #2). One warp per row.
// ---------------------------------------------------------------------------
__global__ void k1f(const float* __restrict__ src,
                    const float* __restrict__ tgt) {
    __shared__ float cs[DIM];
    __shared__ float s1p[8];
    int tid = threadIdx.x, warp = tid >> 5, lane = tid & 31;
    cs[tid] = 0.0f;
    __syncthreads();

    int row = blockIdx.x * 8 + warp;
    const float* p = (row < HALF) ? (src + (size_t)row * DIM)
                                  : (tgt + (size_t)(row - HALF) * DIM);
    const float4* p4 = (const float4*)p;
    float4 v0 = p4[lane];        // cols 4*lane..+3
    float4 v1 = p4[lane + 32];   // cols 128+4*lane..+3

    float ss = v0.x*v0.x + v0.y*v0.y + v0.z*v0.z + v0.w*v0.w
             + v1.x*v1.x + v1.y*v1.y + v1.z*v1.z + v1.w*v1.w;
    #pragma unroll
    for (int o = 16; o; o >>= 1) ss += __shfl_xor_sync(0xffffffffu, ss, o);
    if (lane == 0) { g_sq[row] = ss; s1p[warp] = ss; }

    // fp16 row: lane's v0 quad at byte 8*lane, v1 quad at 256 + 8*lane
    char* base = (char*)g_X + (size_t)row * PROWB + 8 * lane;
    uint2 q0 = { pack_h2(v0.x, v0.y), pack_h2(v0.z, v0.w) };
    uint2 q1 = { pack_h2(v1.x, v1.y), pack_h2(v1.z, v1.w) };
    *(uint2*)(base)       = q0;
    *(uint2*)(base + 256) = q1;

    int c0 = 4 * lane;
    atomicAdd(&cs[c0 + 0], v0.x); atomicAdd(&cs[c0 + 1], v0.y);
    atomicAdd(&cs[c0 + 2], v0.z); atomicAdd(&cs[c0 + 3], v0.w);
    atomicAdd(&cs[128 + c0 + 0], v1.x); atomicAdd(&cs[128 + c0 + 1], v1.y);
    atomicAdd(&cs[128 + c0 + 2], v1.z); atomicAdd(&cs[128 + c0 + 3], v1.w);
    __syncthreads();

    if (tid == 0) {
        double s = 0.0;
        #pragma unroll
        for (int w = 0; w < 8; w++) s += (double)s1p[w];
        atomicAdd(&g_S1, s);
    }
    atomicAdd(&g_colsum[tid], cs[tid]);
}

// ---------------------------------------------------------------------------
// k2: bandwidth closed form (launch #3)
// ---------------------------------------------------------------------------
__global__ void k2_bandwidth() {
    __shared__ float red[DIM];
    int tid = threadIdx.x;
    float c = g_colsum[tid];
    red[tid] = c * c;
    __syncthreads();
    for (int s = 128; s; s >>= 1) { if (tid < s) red[tid] += red[tid + s]; __syncthreads(); }
    if (tid == 0) {
        const double N = (double)NROWS;
        double sum_l2 = 2.0 * N * g_S1 - 2.0 * (double)red[0];
        double bw = sum_l2 / (N * N - N);
        bw = bw / 4.0;                      // KERNEL_MUL^(KERNEL_NUM//2)
        g_negc = (float)(-1.4426950408889634 / (16.0 * bw));
        g_acc = 0.0;
    }
}

// ---------------------------------------------------------------------------
// k3: block-triangular 128x128 Gram GEMM (mma.sync fp16, K=256) + fused RBF
//     epilogue (launch #4 -> profiled). 256 thr, 2x4 warps of 64x32,
//     3-stage cp.async, 2 CTAs/SM.
// ---------------------------------------------------------------------------
__global__ void __launch_bounds__(256, 2) k3_mma() {
    extern __shared__ char dsm[];
    uint32_t smbase = smem_u32(dsm);

    __shared__ float sqic[BM];
    __shared__ float sqjc[BN];
    __shared__ float redw[8];

    int tid = threadIdx.x, wid = tid >> 5, lane = tid & 31;

    // linear block id -> upper-triangle (bi, bj), bj >= bi
    int t = blockIdx.x;
    int bi = 0;
    #pragma unroll 1
    while (t >= NBLK - bi) { t -= NBLK - bi; bi++; }
    int bj = bi + t;
    int i0 = bi * BM, j0 = bj * BN;

    const char* Ag = (const char*)g_X + (size_t)i0 * PROWB;
    const char* Bg = (const char*)g_X + (size_t)j0 * PROWB;

    int lrow = tid >> 3;          // 0..31
    int lq   = tid & 7;
    uint32_t lo0 = (uint32_t)(lrow * 128 + lq * 16);

    auto issue_stage = [&](int ck, int buf) {
        uint32_t smA = smbase + buf * STAGE_BYTES;
        uint32_t smB = smA + 16384;
        const char* ga = Ag + ck * 128 + lq * 16;
        const char* gb = Bg + ck * 128 + lq * 16;
        #pragma unroll
        for (int i = 0; i < 4; i++) {
            uint32_t o = lo0 + (uint32_t)(i * 32 * 128);
            uint32_t sw = o ^ ((o >> 3) & 0x70);
            cp16(smA + sw, ga + (size_t)(lrow + 32 * i) * PROWB);
            cp16(smB + sw, gb + (size_t)(lrow + 32 * i) * PROWB);
        }
    };

    issue_stage(0, 0); CP_COMMIT();
    issue_stage(1, 1); CP_COMMIT();

    float negc = g_negc;
    if (tid < 128) sqic[tid] = g_sq[i0 + tid] * negc;
    else           sqjc[tid - 128] = g_sq[j0 + tid - 128] * negc;

    // warp tiling: 2(m) x 4(n), warp tile 64x32
    int wm = wid >> 2, wn = wid & 3;

    uint32_t arow[4], av[4];
    #pragma unroll
    for (int tm = 0; tm < 4; tm++) {
        uint32_t o = (uint32_t)((wm * 64 + tm * 16 + (lane & 15)) * 128);
        arow[tm] = o; av[tm] = (o >> 3) & 0x70;
    }
    uint32_t brow[2], bv[2];
    #pragma unroll
    for (int tg = 0; tg < 2; tg++) {
        uint32_t o = (uint32_t)((wn * 32 + tg * 16 + (lane & 15)) * 128);
        brow[tg] = o; bv[tg] = (o >> 3) & 0x70;
    }
    uint32_t ksel = (uint32_t)(lane & 16);

    float acc[4][4][4];
    #pragma unroll
    for (int a = 0; a < 4; a++)
        #pragma unroll
        for (int b = 0; b < 4; b++)
            #pragma unroll
            for (int e = 0; e < 4; e++) acc[a][b][e] = 0.0f;

    int buf = 0, ldbuf = 2;
    for (int it = 0; it < KTILES; it++) {
        CP_WAIT1();
        __syncthreads();

        int ld = it + NSTAGE - 1;
        if (ld < KTILES) issue_stage(ld, ldbuf);
        CP_COMMIT();

        uint32_t smA = smbase + buf * STAGE_BYTES;
        uint32_t smB = smA + 16384;

        #pragma unroll
        for (int ks = 0; ks < 4; ks++) {
            uint32_t kb = (uint32_t)(ks * 32) + ksel;
            uint32_t a[4][4], b[2][4];
            #pragma unroll
            for (int tm = 0; tm < 4; tm++)
                ldsm4(a[tm], smA + arow[tm] + (kb ^ av[tm]));
            #pragma unroll
            for (int tg = 0; tg < 2; tg++)
                ldsm4(b[tg], smB + brow[tg] + (kb ^ bv[tg]));
            #pragma unroll
            for (int tm = 0; tm < 4; tm++) {
                mma16816(acc[tm][0], a[tm], b[0][0], b[0][2]);
                mma16816(acc[tm][1], a[tm], b[0][1], b[0][3]);
                mma16816(acc[tm][2], a[tm], b[1][0], b[1][2]);
                mma16816(acc[tm][3], a[tm], b[1][1], b[1][3]);
            }
        }
        buf = (buf == NSTAGE - 1) ? 0 : buf + 1;
        ldbuf = (ldbuf == NSTAGE - 1) ? 0 : ldbuf + 1;
    }

    // fused RBF epilogue: l2 = sqi + sqj - 2 dot; u = ex2(arg);
    // kernel sum = u + u^2 + u^4 + u^8 + u^16
    float twoc = -2.0f * negc;
    float tsum = 0.0f;
    #pragma unroll
    for (int tm = 0; tm < 4; tm++) {
        int mb = wm * 64 + tm * 16 + (lane >> 2);
        float si0 = sqic[mb], si8 = sqic[mb + 8];
        #pragma unroll
        for (int tn = 0; tn < 4; tn++) {
            int nb = wn * 32 + tn * 8 + (lane & 3) * 2;
            float sj0 = sqjc[nb], sj1 = sqjc[nb + 1];
            float* cc = acc[tm][tn];
            float base[4] = { si0 + sj0, si0 + sj1, si8 + sj0, si8 + sj1 };
            #pragma unroll
            for (int e = 0; e < 4; e++) {
                float arg = fmaf(cc[e], twoc, base[e]);
                float u = ex2f(arg);
                float u2 = u * u, u4 = u2 * u2, u8 = u4 * u4, u16 = u8 * u8;
                tsum += ((u + u2) + (u4 + u8)) + u16;
            }
        }
    }
    #pragma unroll
    for (int o = 16; o; o >>= 1) tsum += __shfl_xor_sync(0xffffffffu, tsum, o);
    if (lane == 0) redw[wid] = tsum;
    __syncthreads();
    if (tid == 0) {
        float s = ((redw[0] + redw[1]) + (redw[2] + redw[3]))
                + ((redw[4] + redw[5]) + (redw[6] + redw[7]));
        float w = ((i0 < HALF) == (j0 < HALF)) ? 1.0f : -1.0f;
        if (bi != bj) w *= 2.0f;
        atomicAdd(&g_acc, (double)(s * w));
    }
}

// ---------------------------------------------------------------------------
// k4: finalize mean (launch #5)
// ---------------------------------------------------------------------------
__global__ void k4_final(float* out) {
    if (threadIdx.x == 0)
        out[0] = (float)(g_acc / ((double)HALF * (double)HALF));
}

extern "C" void kernel_launch(void* const* d_in, const int* in_sizes, int n_in,
                              void* d_out, int out_size) {
    const float* src = (const float*)d_in[0];
    const float* tgt = (const float*)d_in[1];
    float* out = (float*)d_out;

    cudaFuncSetAttribute(k3_mma, cudaFuncAttributeMaxDynamicSharedMemorySize, DSM_BYTES);

    k0_zero<<<1, 256>>>();
    k1f<<<NROWS / 8, 256>>>(src, tgt);
    k2_bandwidth<<<1, 256>>>();
    k3_mma<<<NTILES, 256, DSM_BYTES>>>();
    k4_final<<<1, 32>>>(out);
}

// round 14
// speedup vs baseline: 4.0353x; 1.0419x over previous
#include <cuda_runtime.h>
#include <cuda_fp16.h>
#include <cstdint>

// ---------------- problem constants ----------------
#define NROWS 8192           // 2 * 4096
#define HALF  4096
#define DIM   256
#define PROWB 512            // physical row bytes: 256 fp16
#define KTILES 4             // K = 256 fp16, chunks of 64 (128B)
#define BM 128
#define BN 128
#define NSTAGE 3
#define NBLK 64
#define NTILES (NBLK * (NBLK + 1) / 2)   // 2080
#define K1BLOCKS (NROWS / 8)             // 1024

#define STAGE_BYTES 32768    // A 16KB + B 16KB
#define DSM_BYTES (NSTAGE * STAGE_BYTES) // 96KB -> 2 CTAs/SM

// ---------------- device scratch ----------------
__device__ float  g_pcs[K1BLOCKS * DIM];  // per-block partial colsums (1MB)
__device__ float  g_ps1[K1BLOCKS];        // per-block partial sumsq sums
__device__ float  g_sq[NROWS];
__device__ float  g_negc;                 // -log2(e)/(16*bandwidth)
__device__ double g_acc;
__device__ int    g_done;
__device__ __align__(16) __half g_X[(size_t)NROWS * DIM];  // fp16 rows (4MB)

// ---------------- PTX helpers (base ISA only) ----------------
__device__ __forceinline__ float ex2f(float x) {
    float y; asm("ex2.approx.f32 %0, %1;" : "=f"(y) : "f"(x)); return y;
}
__device__ __forceinline__ uint32_t smem_u32(const void* p) {
    uint32_t a;
    asm("{ .reg .u64 t; cvta.to.shared.u64 t, %1; cvt.u32.u64 %0, t; }" : "=r"(a) : "l"(p));
    return a;
}
__device__ __forceinline__ void cp16(uint32_t saddr, const void* g) {
    asm volatile("cp.async.cg.shared.global [%0], [%1], 16;" :: "r"(saddr), "l"(g));
}
#define CP_COMMIT() asm volatile("cp.async.commit_group;" ::: "memory")
#define CP_WAIT1()  asm volatile("cp.async.wait_group 1;" ::: "memory")

__device__ __forceinline__ void ldsm4(uint32_t* r, uint32_t addr) {
    asm volatile("ldmatrix.sync.aligned.m8n8.x4.shared.b16 {%0,%1,%2,%3}, [%4];"
        : "=r"(r[0]), "=r"(r[1]), "=r"(r[2]), "=r"(r[3]) : "r"(addr));
}
__device__ __forceinline__ void mma16816(float* c, const uint32_t* a,
                                         uint32_t b0, uint32_t b1) {
    asm volatile(
        "mma.sync.aligned.m16n8k16.row.col.f32.f16.f16.f32 "
        "{%0,%1,%2,%3}, {%4,%5,%6,%7}, {%8,%9}, {%0,%1,%2,%3};"
        : "+f"(c[0]), "+f"(c[1]), "+f"(c[2]), "+f"(c[3])
        : "r"(a[0]), "r"(a[1]), "r"(a[2]), "r"(a[3]), "r"(b0), "r"(b1));
}
__device__ __forceinline__ uint32_t pack_h2(float x, float y) {
    __half2 t = __floats2half2_rn(x, y);
    return *reinterpret_cast<uint32_t*>(&t);
}

// ---------------------------------------------------------------------------
// k1f (launch #1): rowstats + fp16 convert + per-block partials (no atomics)
// 1024 blocks x 256 threads, one warp per row.
// ---------------------------------------------------------------------------
__global__ void k1f(const float* __restrict__ src,
                    const float* __restrict__ tgt) {
    __shared__ float cs[8][DIM];     // per-warp colsums
    __shared__ float s1p[8];
    int tid = threadIdx.x, warp = tid >> 5, lane = tid & 31;

    int row = blockIdx.x * 8 + warp;
    const float* p = (row < HALF) ? (src + (size_t)row * DIM)
                                  : (tgt + (size_t)(row - HALF) * DIM);
    const float4* p4 = (const float4*)p;
    float4 v0 = p4[lane];        // cols 4*lane..+3
    float4 v1 = p4[lane + 32];   // cols 128+4*lane..+3

    float ss = v0.x*v0.x + v0.y*v0.y + v0.z*v0.z + v0.w*v0.w
             + v1.x*v1.x + v1.y*v1.y + v1.z*v1.z + v1.w*v1.w;
    #pragma unroll
    for (int o = 16; o; o >>= 1) ss += __shfl_xor_sync(0xffffffffu, ss, o);
    if (lane == 0) { g_sq[row] = ss; s1p[warp] = ss; }

    // fp16 row
    char* base = (char*)g_X + (size_t)row * PROWB + 8 * lane;
    uint2 q0 = { pack_h2(v0.x, v0.y), pack_h2(v0.z, v0.w) };
    uint2 q1 = { pack_h2(v1.x, v1.y), pack_h2(v1.z, v1.w) };
    *(uint2*)(base)       = q0;
    *(uint2*)(base + 256) = q1;

    // per-warp colsum slots (no conflicts: each lane owns distinct columns)
    int c0 = 4 * lane;
    cs[warp][c0 + 0] = v0.x; cs[warp][c0 + 1] = v0.y;
    cs[warp][c0 + 2] = v0.z; cs[warp][c0 + 3] = v0.w;
    cs[warp][128 + c0 + 0] = v1.x; cs[warp][128 + c0 + 1] = v1.y;
    cs[warp][128 + c0 + 2] = v1.z; cs[warp][128 + c0 + 3] = v1.w;
    __syncthreads();

    // block reduce: thread tid sums its column over 8 warps -> global partial
    float s = ((cs[0][tid] + cs[1][tid]) + (cs[2][tid] + cs[3][tid]))
            + ((cs[4][tid] + cs[5][tid]) + (cs[6][tid] + cs[7][tid]));
    g_pcs[blockIdx.x * DIM + tid] = s;

    if (tid == 0) {
        float t = ((s1p[0] + s1p[1]) + (s1p[2] + s1p[3]))
                + ((s1p[4] + s1p[5]) + (s1p[6] + s1p[7]));
        g_ps1[blockIdx.x] = t;
    }
}

// ---------------------------------------------------------------------------
// k2 (launch #2): reduce partials -> bandwidth; reset accumulators.
// 1 block x 1024 threads.
// ---------------------------------------------------------------------------
__global__ void k2_bandwidth() {
    __shared__ float  csred[4][DIM];     // 4 partial slices per column
    __shared__ double s1red[32];
    __shared__ float  sqred[DIM];

    int tid = threadIdx.x;
    int col = tid & (DIM - 1);
    int part = tid >> 8;                 // 0..3

    // colsum: each thread sums 256 blocks of its slice
    float s = 0.0f;
    #pragma unroll 8
    for (int b = 0; b < K1BLOCKS / 4; b++)
        s += g_pcs[(part * (K1BLOCKS / 4) + b) * DIM + col];
    csred[part][col] = s;

    // S1: thread t sums g_ps1[t] (1024 entries), warp-reduce in double
    double d = (double)g_ps1[tid];
    #pragma unroll
    for (int o = 16; o; o >>= 1) d += __shfl_xor_sync(0xffffffffu, d, o);
    if ((tid & 31) == 0) s1red[tid >> 5] = d;
    __syncthreads();

    if (tid < DIM) {
        float c = ((csred[0][tid] + csred[1][tid]) + (csred[2][tid] + csred[3][tid]));
        sqred[tid] = c * c;
    }
    __syncthreads();
    for (int st = 128; st; st >>= 1) {
        if (tid < st) sqred[tid] += sqred[tid + st];
        __syncthreads();
    }
    if (tid == 0) {
        double S1 = 0.0;
        #pragma unroll
        for (int w = 0; w < 32; w++) S1 += s1red[w];
        const double N = (double)NROWS;
        double sum_l2 = 2.0 * N * S1 - 2.0 * (double)sqred[0];
        double bw = sum_l2 / (N * N - N);
        bw = bw / 4.0;                      // KERNEL_MUL^(KERNEL_NUM//2)
        g_negc = (float)(-1.4426950408889634 / (16.0 * bw));
        g_acc = 0.0;
        g_done = 0;
    }
}

// ---------------------------------------------------------------------------
// k3 (launch #3): block-triangular 128x128 Gram GEMM (mma.sync fp16, K=256)
// + fused RBF epilogue + last-block finalize. 256 thr, 2x4 warps of 64x32,
// 3-stage cp.async, 2 CTAs/SM.
// ---------------------------------------------------------------------------
__global__ void __launch_bounds__(256, 2) k3_mma(float* __restrict__ out) {
    extern __shared__ char dsm[];
    uint32_t smbase = smem_u32(dsm);

    __shared__ float sqic[BM];
    __shared__ float sqjc[BN];
    __shared__ float redw[8];

    int tid = threadIdx.x, wid = tid >> 5, lane = tid & 31;

    // linear block id -> upper-triangle (bi, bj), bj >= bi
    int t = blockIdx.x;
    int bi = 0;
    #pragma unroll 1
    while (t >= NBLK - bi) { t -= NBLK - bi; bi++; }
    int bj = bi + t;
    int i0 = bi * BM, j0 = bj * BN;

    const char* Ag = (const char*)g_X + (size_t)i0 * PROWB;
    const char* Bg = (const char*)g_X + (size_t)j0 * PROWB;

    int lrow = tid >> 3;          // 0..31
    int lq   = tid & 7;
    uint32_t lo0 = (uint32_t)(lrow * 128 + lq * 16);

    auto issue_stage = [&](int ck, int buf) {
        uint32_t smA = smbase + buf * STAGE_BYTES;
        uint32_t smB = smA + 16384;
        const char* ga = Ag + ck * 128 + lq * 16;
        const char* gb = Bg + ck * 128 + lq * 16;
        #pragma unroll
        for (int i = 0; i < 4; i++) {
            uint32_t o = lo0 + (uint32_t)(i * 32 * 128);
            uint32_t sw = o ^ ((o >> 3) & 0x70);
            cp16(smA + sw, ga + (size_t)(lrow + 32 * i) * PROWB);
            cp16(smB + sw, gb + (size_t)(lrow + 32 * i) * PROWB);
        }
    };

    issue_stage(0, 0); CP_COMMIT();
    issue_stage(1, 1); CP_COMMIT();

    float negc = g_negc;
    if (tid < 128) sqic[tid] = g_sq[i0 + tid] * negc;
    else           sqjc[tid - 128] = g_sq[j0 + tid - 128] * negc;

    // warp tiling: 2(m) x 4(n), warp tile 64x32
    int wm = wid >> 2, wn = wid & 3;

    uint32_t arow[4], av[4];
    #pragma unroll
    for (int tm = 0; tm < 4; tm++) {
        uint32_t o = (uint32_t)((wm * 64 + tm * 16 + (lane & 15)) * 128);
        arow[tm] = o; av[tm] = (o >> 3) & 0x70;
    }
    uint32_t brow[2], bv[2];
    #pragma unroll
    for (int tg = 0; tg < 2; tg++) {
        uint32_t o = (uint32_t)((wn * 32 + tg * 16 + (lane & 15)) * 128);
        brow[tg] = o; bv[tg] = (o >> 3) & 0x70;
    }
    uint32_t ksel = (uint32_t)(lane & 16);

    float acc[4][4][4];
    #pragma unroll
    for (int a = 0; a < 4; a++)
        #pragma unroll
        for (int b = 0; b < 4; b++)
            #pragma unroll
            for (int e = 0; e < 4; e++) acc[a][b][e] = 0.0f;

    int buf = 0, ldbuf = 2;
    for (int it = 0; it < KTILES; it++) {
        CP_WAIT1();
        __syncthreads();

        int ld = it + NSTAGE - 1;
        if (ld < KTILES) issue_stage(ld, ldbuf);
        CP_COMMIT();

        uint32_t smA = smbase + buf * STAGE_BYTES;
        uint32_t smB = smA + 16384;

        #pragma unroll
        for (int ks = 0; ks < 4; ks++) {
            uint32_t kb = (uint32_t)(ks * 32) + ksel;
            uint32_t a[4][4], b[2][4];
            #pragma unroll
            for (int tm = 0; tm < 4; tm++)
                ldsm4(a[tm], smA + arow[tm] + (kb ^ av[tm]));
            #pragma unroll
            for (int tg = 0; tg < 2; tg++)
                ldsm4(b[tg], smB + brow[tg] + (kb ^ bv[tg]));
            #pragma unroll
            for (int tm = 0; tm < 4; tm++) {
                mma16816(acc[tm][0], a[tm], b[0][0], b[0][2]);
                mma16816(acc[tm][1], a[tm], b[0][1], b[0][3]);
                mma16816(acc[tm][2], a[tm], b[1][0], b[1][2]);
                mma16816(acc[tm][3], a[tm], b[1][1], b[1][3]);
            }
        }
        buf = (buf == NSTAGE - 1) ? 0 : buf + 1;
        ldbuf = (ldbuf == NSTAGE - 1) ? 0 : ldbuf + 1;
    }

    // fused RBF epilogue: l2 = sqi + sqj - 2 dot; u = ex2(arg);
    // kernel sum = u + u^2 + u^4 + u^8 + u^16
    float twoc = -2.0f * negc;
    float tsum = 0.0f;
    #pragma unroll
    for (int tm = 0; tm < 4; tm++) {
        int mb = wm * 64 + tm * 16 + (lane >> 2);
        float si0 = sqic[mb], si8 = sqic[mb + 8];
        #pragma unroll
        for (int tn = 0; tn < 4; tn++) {
            int nb = wn * 32 + tn * 8 + (lane & 3) * 2;
            float sj0 = sqjc[nb], sj1 = sqjc[nb + 1];
            float* cc = acc[tm][tn];
            float base[4] = { si0 + sj0, si0 + sj1, si8 + sj0, si8 + sj1 };
            #pragma unroll
            for (int e = 0; e < 4; e++) {
                float arg = fmaf(cc[e], twoc, base[e]);
                float u = ex2f(arg);
                float u2 = u * u, u4 = u2 * u2, u8 = u4 * u4, u16 = u8 * u8;
                tsum += ((u + u2) + (u4 + u8)) + u16;
            }
        }
    }
    #pragma unroll
    for (int o = 16; o; o >>= 1) tsum += __shfl_xor_sync(0xffffffffu, tsum, o);
    if (lane == 0) redw[wid] = tsum;
    __syncthreads();
    if (tid == 0) {
        float s = ((redw[0] + redw[1]) + (redw[2] + redw[3]))
                + ((redw[4] + redw[5]) + (redw[6] + redw[7]));
        float w = ((i0 < HALF) == (j0 < HALF)) ? 1.0f : -1.0f;
        if (bi != bj) w *= 2.0f;
        atomicAdd(&g_acc, (double)(s * w));
        __threadfence();
        int done = atomicAdd(&g_done, 1);
        if (done == NTILES - 1) {
            double total = atomicAdd(&g_acc, 0.0);   // fenced read
            out[0] = (float)(total / ((double)HALF * (double)HALF));
        }
    }
}

extern "C" void kernel_launch(void* const* d_in, const int* in_sizes, int n_in,
                              void* d_out, int out_size) {
    const float* src = (const float*)d_in[0];
    const float* tgt = (const float*)d_in[1];
    float* out = (float*)d_out;

    cudaFuncSetAttribute(k3_mma, cudaFuncAttributeMaxDynamicSharedMemorySize, DSM_BYTES);

    k1f<<<K1BLOCKS, 256>>>(src, tgt);
    k2_bandwidth<<<1, 1024>>>();
    k3_mma<<<NTILES, 256, DSM_BYTES>>>(out);
}

// round 16
// speedup vs baseline: 4.4028x; 1.0911x over previous
#include <cuda_runtime.h>
#include <cuda_fp16.h>
#include <cstdint>

// ---------------- problem constants ----------------
#define NROWS 8192           // 2 * 4096
#define HALF  4096
#define DIM   256
#define PROWB 512            // physical row bytes: 256 fp16
#define KTILES 4             // K = 256 fp16, chunks of 64 (128B)
#define BM 128
#define BN 256
#define NSTAGE 2
#define NTILES2 1056         // sum_{bi<64} (32 - bi/2)
#define K1BLOCKS 256         // 32 rows per block

#define STAGE_BYTES 49152    // A 16KB + B 32KB
#define DSM_BYTES (NSTAGE * STAGE_BYTES)   // 96KB -> 2 CTAs/SM

// ---------------- device scratch ----------------
__device__ float  g_pcs[K1BLOCKS * DIM];  // per-block partial colsums (256KB)
__device__ float  g_ps1[K1BLOCKS];        // per-block partial sumsq sums
__device__ float  g_sq[NROWS];
__device__ float  g_negc;                 // -log2(e)/(16*bandwidth)
__device__ double g_acc;
__device__ int    g_done;
__device__ __align__(16) __half g_X[(size_t)NROWS * DIM];  // fp16 rows (4MB)

// ---------------- PTX helpers (base ISA only) ----------------
__device__ __forceinline__ float ex2f(float x) {
    float y; asm("ex2.approx.f32 %0, %1;" : "=f"(y) : "f"(x)); return y;
}
__device__ __forceinline__ uint32_t smem_u32(const void* p) {
    uint32_t a;
    asm("{ .reg .u64 t; cvta.to.shared.u64 t, %1; cvt.u32.u64 %0, t; }" : "=r"(a) : "l"(p));
    return a;
}
__device__ __forceinline__ void cp16(uint32_t saddr, const void* g) {
    asm volatile("cp.async.cg.shared.global [%0], [%1], 16;" :: "r"(saddr), "l"(g));
}
#define CP_COMMIT() asm volatile("cp.async.commit_group;" ::: "memory")
#define CP_WAIT1()  asm volatile("cp.async.wait_group 1;" ::: "memory")

__device__ __forceinline__ void ldsm4(uint32_t* r, uint32_t addr) {
    asm volatile("ldmatrix.sync.aligned.m8n8.x4.shared.b16 {%0,%1,%2,%3}, [%4];"
        : "=r"(r[0]), "=r"(r[1]), "=r"(r[2]), "=r"(r[3]) : "r"(addr));
}
// fp16-accumulator MMA: D(f16x2 x2) = A(f16) * B(f16) + C
__device__ __forceinline__ void mma16816h(uint32_t* c, const uint32_t* a,
                                          uint32_t b0, uint32_t b1) {
    asm volatile(
        "mma.sync.aligned.m16n8k16.row.col.f16.f16.f16.f16 "
        "{%0,%1}, {%2,%3,%4,%5}, {%6,%7}, {%0,%1};"
        : "+r"(c[0]), "+r"(c[1])
        : "r"(a[0]), "r"(a[1]), "r"(a[2]), "r"(a[3]), "r"(b0), "r"(b1));
}
__device__ __forceinline__ uint32_t pack_h2(float x, float y) {
    __half2 t = __floats2half2_rn(x, y);
    return *reinterpret_cast<uint32_t*>(&t);
}

// ---------------------------------------------------------------------------
// k1f (launch #1): rowstats + fp16 convert + per-block partials.
// 256 blocks x 256 threads; each warp handles 4 rows (MLP).
// ---------------------------------------------------------------------------
__global__ void k1f(const float* __restrict__ src,
                    const float* __restrict__ tgt) {
    __shared__ float cs[8][DIM];
    __shared__ float s1p[8];
    int tid = threadIdx.x, warp = tid >> 5, lane = tid & 31;

    int row0 = blockIdx.x * 32 + warp * 4;
    float4 v0[4], v1[4];
    #pragma unroll
    for (int r = 0; r < 4; r++) {
        int row = row0 + r;
        const float* p = (row < HALF) ? (src + (size_t)row * DIM)
                                      : (tgt + (size_t)(row - HALF) * DIM);
        const float4* p4 = (const float4*)p;
        v0[r] = p4[lane];
        v1[r] = p4[lane + 32];
    }

    float csA[4] = {0, 0, 0, 0}, csB[4] = {0, 0, 0, 0};
    float ss_tot = 0.0f;
    #pragma unroll
    for (int r = 0; r < 4; r++) {
        int row = row0 + r;
        float ss = v0[r].x*v0[r].x + v0[r].y*v0[r].y + v0[r].z*v0[r].z + v0[r].w*v0[r].w
                 + v1[r].x*v1[r].x + v1[r].y*v1[r].y + v1[r].z*v1[r].z + v1[r].w*v1[r].w;
        #pragma unroll
        for (int o = 16; o; o >>= 1) ss += __shfl_xor_sync(0xffffffffu, ss, o);
        if (lane == 0) g_sq[row] = ss;
        ss_tot += ss;                     // full value in every lane

        char* base = (char*)g_X + (size_t)row * PROWB + 8 * lane;
        uint2 q0 = { pack_h2(v0[r].x, v0[r].y), pack_h2(v0[r].z, v0[r].w) };
        uint2 q1 = { pack_h2(v1[r].x, v1[r].y), pack_h2(v1[r].z, v1[r].w) };
        *(uint2*)(base)       = q0;
        *(uint2*)(base + 256) = q1;

        csA[0] += v0[r].x; csA[1] += v0[r].y; csA[2] += v0[r].z; csA[3] += v0[r].w;
        csB[0] += v1[r].x; csB[1] += v1[r].y; csB[2] += v1[r].z; csB[3] += v1[r].w;
    }

    int c0 = 4 * lane;
    #pragma unroll
    for (int k = 0; k < 4; k++) {
        cs[warp][c0 + k]       = csA[k];
        cs[warp][128 + c0 + k] = csB[k];
    }
    if (lane == 0) s1p[warp] = ss_tot;
    __syncthreads();

    float s = ((cs[0][tid] + cs[1][tid]) + (cs[2][tid] + cs[3][tid]))
            + ((cs[4][tid] + cs[5][tid]) + (cs[6][tid] + cs[7][tid]));
    g_pcs[blockIdx.x * DIM + tid] = s;

    if (tid == 0) {
        float t = ((s1p[0] + s1p[1]) + (s1p[2] + s1p[3]))
                + ((s1p[4] + s1p[5]) + (s1p[6] + s1p[7]));
        g_ps1[blockIdx.x] = t;
    }
}

// ---------------------------------------------------------------------------
// k2 (launch #2): reduce 256 partials -> bandwidth; reset accumulators.
// 1 block x 1024 threads (reads 256KB).
// ---------------------------------------------------------------------------
__global__ void k2_bandwidth() {
    __shared__ float  csred[4][DIM];
    __shared__ double s1red[8];
    __shared__ float  sqred[DIM];

    int tid = threadIdx.x;
    int col = tid & (DIM - 1);
    int part = tid >> 8;                 // 0..3

    float s = 0.0f;
    #pragma unroll 8
    for (int b = 0; b < K1BLOCKS / 4; b++)
        s += g_pcs[(part * (K1BLOCKS / 4) + b) * DIM + col];
    csred[part][col] = s;

    if (tid < K1BLOCKS) {
        double d = (double)g_ps1[tid];
        #pragma unroll
        for (int o = 16; o; o >>= 1) d += __shfl_xor_sync(0xffffffffu, d, o);
        if ((tid & 31) == 0) s1red[tid >> 5] = d;
    }
    __syncthreads();

    if (tid < DIM) {
        float c = (csred[0][tid] + csred[1][tid]) + (csred[2][tid] + csred[3][tid]);
        sqred[tid] = c * c;
    }
    __syncthreads();
    for (int st = 128; st; st >>= 1) {
        if (tid < st) sqred[tid] += sqred[tid + st];
        __syncthreads();
    }
    if (tid == 0) {
        double S1 = 0.0;
        #pragma unroll
        for (int w = 0; w < 8; w++) S1 += s1red[w];
        const double N = (double)NROWS;
        double sum_l2 = 2.0 * N * S1 - 2.0 * (double)sqred[0];
        double bw = sum_l2 / (N * N - N);
        bw = bw / 4.0;                      // KERNEL_MUL^(KERNEL_NUM//2)
        g_negc = (float)(-1.4426950408889634 / (16.0 * bw));
        g_acc = 0.0;
        g_done = 0;
    }
}

// ---------------------------------------------------------------------------
// k3 (launch #3): block-triangular 128x256 Gram GEMM, fp16 acc, 64x64 warp
// tiles (2m x 4n), K=256, 2-stage cp.async, 2 CTAs/SM, fused RBF epilogue
// + last-block finalize.
// ---------------------------------------------------------------------------
__global__ void __launch_bounds__(256, 2) k3_mma(float* __restrict__ out) {
    extern __shared__ char dsm[];
    uint32_t smbase = smem_u32(dsm);

    __shared__ float sqic[BM];
    __shared__ float sqjc[BN];
    __shared__ float redw[8];

    int tid = threadIdx.x, wid = tid >> 5, lane = tid & 31;

    // map linear id -> (bi 128-row block, c 256-col block), 2c+1 >= bi
    int t = blockIdx.x;
    int bi = 0, cnt = 32;
    #pragma unroll 1
    while (t >= cnt) { t -= cnt; bi++; cnt = 32 - (bi >> 1); }
    int c = (bi >> 1) + t;
    int i0 = bi * BM, j0 = c * BN;

    const char* Ag = (const char*)g_X + (size_t)i0 * PROWB;
    const char* Bg = (const char*)g_X + (size_t)j0 * PROWB;

    int lrow = tid >> 3;          // 0..31
    int lq   = tid & 7;
    uint32_t lo0 = (uint32_t)(lrow * 128 + lq * 16);

    auto issue_stage = [&](int ck, int buf) {
        uint32_t smA = smbase + buf * STAGE_BYTES;
        uint32_t smB = smA + 16384;
        const char* ga = Ag + ck * 128 + lq * 16;
        const char* gb = Bg + ck * 128 + lq * 16;
        #pragma unroll
        for (int i = 0; i < 4; i++) {
            uint32_t o = lo0 + (uint32_t)(i * 32 * 128);
            uint32_t sw = o ^ ((o >> 3) & 0x70);
            cp16(smA + sw, ga + (size_t)(lrow + 32 * i) * PROWB);
        }
        #pragma unroll
        for (int i = 0; i < 8; i++) {
            uint32_t o = lo0 + (uint32_t)(i * 32 * 128);
            uint32_t sw = o ^ ((o >> 3) & 0x70);
            cp16(smB + sw, gb + (size_t)(lrow + 32 * i) * PROWB);
        }
    };

    issue_stage(0, 0); CP_COMMIT();
    issue_stage(1, 1); CP_COMMIT();

    float negc = g_negc;
    sqjc[tid] = g_sq[j0 + tid] * negc;
    if (tid < 128) sqic[tid] = g_sq[i0 + tid] * negc;

    // warp tiling: 2(m) x 4(n), warp tile 64x64
    int wm = wid >> 2, wn = wid & 3;

    uint32_t arow[4], av[4];
    #pragma unroll
    for (int tm = 0; tm < 4; tm++) {
        uint32_t o = (uint32_t)((wm * 64 + tm * 16 + (lane & 15)) * 128);
        arow[tm] = o; av[tm] = (o >> 3) & 0x70;
    }
    uint32_t brow[4], bv[4];
    #pragma unroll
    for (int tg = 0; tg < 4; tg++) {
        uint32_t o = (uint32_t)((wn * 64 + tg * 16 + (lane & 15)) * 128);
        brow[tg] = o; bv[tg] = (o >> 3) & 0x70;
    }
    uint32_t ksel = (uint32_t)(lane & 16);

    uint32_t acc[4][8][2];      // [tm][tn][2]  fp16x2 accumulators
    #pragma unroll
    for (int a = 0; a < 4; a++)
        #pragma unroll
        for (int b = 0; b < 8; b++) { acc[a][b][0] = 0u; acc[a][b][1] = 0u; }

    for (int it = 0; it < KTILES; it++) {
        CP_WAIT1();
        __syncthreads();

        uint32_t smA = smbase + (it & 1) * STAGE_BYTES;
        uint32_t smB = smA + 16384;

        #pragma unroll
        for (int ks = 0; ks < 4; ks++) {
            uint32_t kb = (uint32_t)(ks * 32) + ksel;
            uint32_t a[4][4], b[4][4];
            #pragma unroll
            for (int tm = 0; tm < 4; tm++)
                ldsm4(a[tm], smA + arow[tm] + (kb ^ av[tm]));
            #pragma unroll
            for (int tg = 0; tg < 4; tg++)
                ldsm4(b[tg], smB + brow[tg] + (kb ^ bv[tg]));
            #pragma unroll
            for (int tm = 0; tm < 4; tm++)
                #pragma unroll
                for (int tg = 0; tg < 4; tg++) {
                    mma16816h(acc[tm][2*tg],     a[tm], b[tg][0], b[tg][2]);
                    mma16816h(acc[tm][2*tg + 1], a[tm], b[tg][1], b[tg][3]);
                }
        }
        __syncthreads();
        if (it + 2 < KTILES) { issue_stage(it + 2, it & 1); CP_COMMIT(); }
    }

    // per-warp weight by column 128-block h = 2c + (wn>>1)
    int h = 2 * c + (wn >> 1);
    float w = (h < bi) ? 0.0f : ((h == bi) ? 1.0f : 2.0f);
    float sign = ((bi < 32) == (h < 32)) ? 1.0f : -1.0f;

    // fused RBF epilogue
    float twoc = -2.0f * negc;
    float tsum = 0.0f;
    #pragma unroll
    for (int tm = 0; tm < 4; tm++) {
        int mb = wm * 64 + tm * 16 + (lane >> 2);
        float si0 = sqic[mb], si8 = sqic[mb + 8];
        #pragma unroll
        for (int tn = 0; tn < 8; tn++) {
            int nb = wn * 64 + tn * 8 + (lane & 3) * 2;
            float sj0 = sqjc[nb], sj1 = sqjc[nb + 1];
            float2 lo = __half22float2(*(__half2*)&acc[tm][tn][0]);  // row mb
            float2 hi = __half22float2(*(__half2*)&acc[tm][tn][1]);  // row mb+8
            float d0 = lo.x, d1 = lo.y, d2 = hi.x, d3 = hi.y;
            float base[4] = { si0 + sj0, si0 + sj1, si8 + sj0, si8 + sj1 };
            float dd[4] = { d0, d1, d2, d3 };
            #pragma unroll
            for (int e = 0; e < 4; e++) {
                float arg = fmaf(dd[e], twoc, base[e]);
                float u = ex2f(arg);
                float u2 = u * u, u4 = u2 * u2, u8 = u4 * u4, u16 = u8 * u8;
                tsum += ((u + u2) + (u4 + u8)) + u16;
            }
        }
    }
    #pragma unroll
    for (int o = 16; o; o >>= 1) tsum += __shfl_xor_sync(0xffffffffu, tsum, o);
    if (lane == 0) redw[wid] = tsum * w * sign;
    __syncthreads();
    if (tid == 0) {
        float s = ((redw[0] + redw[1]) + (redw[2] + redw[3]))
                + ((redw[4] + redw[5]) + (redw[6] + redw[7]));
        atomicAdd(&g_acc, (double)s);
        __threadfence();
        int done = atomicAdd(&g_done, 1);
        if (done == NTILES2 - 1) {
            double total = atomicAdd(&g_acc, 0.0);   // fenced read
            out[0] = (float)(total / ((double)HALF * (double)HALF));
        }
    }
}

extern "C" void kernel_launch(void* const* d_in, const int* in_sizes, int n_in,
                              void* d_out, int out_size) {
    const float* src = (const float*)d_in[0];
    const float* tgt = (const float*)d_in[1];
    float* out = (float*)d_out;

    cudaFuncSetAttribute(k3_mma, cudaFuncAttributeMaxDynamicSharedMemorySize, DSM_BYTES);

    k1f<<<K1BLOCKS, 256>>>(src, tgt);
    k2_bandwidth<<<1, 1024>>>();
    k3_mma<<<NTILES2, 256, DSM_BYTES>>>(out);
}